// round 12
// baseline (speedup 1.0000x reference)
#include <cuda_runtime.h>
#include <cstdint>
#include <math.h>

#define Bc 8
#define Nc 2048
#define Kc 20
#define EMBc 1024
#define EPSc 1e-5
#define SLOPEc 0.2f
#define MSPLIT 4

typedef unsigned long long u64;

// ---------------- packed f32x2 helpers (exact dual IEEE fp32 ops) ----------------
__device__ __forceinline__ u64 pack2(float lo, float hi)
{
    u64 r; asm("mov.b64 %0, {%1, %2};" : "=l"(r) : "f"(lo), "f"(hi)); return r;
}
__device__ __forceinline__ void unpack2(u64 v, float& lo, float& hi)
{
    asm("mov.b64 {%0, %1}, %2;" : "=f"(lo), "=f"(hi) : "l"(v));
}
__device__ __forceinline__ u64 fma2(u64 a, u64 b, u64 c)
{
    u64 d; asm("fma.rn.f32x2 %0, %1, %2, %3;" : "=l"(d) : "l"(a), "l"(b), "l"(c)); return d;
}
__device__ __forceinline__ u64 add2(u64 a, u64 b)
{
    u64 d; asm("add.rn.f32x2 %0, %1, %2;" : "=l"(d) : "l"(a), "l"(b)); return d;
}
__device__ __forceinline__ u64 sub2(u64 a, u64 b)
{
    return fma2(b, 0xBF800000BF800000ull, a);
}

// ---------------- scratch ----------------
__device__ float2 g_pv[(size_t)Bc * Nc * MSPLIT * Kc];   // partial top-20 values
__device__ int    g_pi[(size_t)Bc * Nc * MSPLIT * Kc];   // partial top-20 indices
__device__ float2 g_xx2[Bc * Nc];
__device__ int    g_idx[Bc * Nc * Kc];
__device__ float  g_x1[Bc * 64 * Nc];
__device__ float  g_x2[Bc * 64 * Nc];
__device__ float  g_x3[Bc * 128 * Nc];
__device__ float  g_x4[Bc * 256 * Nc];
__device__ float  g_wT[90496];
__device__ float  g_ymax[Bc * Nc * 256];
__device__ double g_statsd[3072];
__device__ float  g_z5[Bc * EMBc * Nc];
__device__ float  g_p[Bc * 2 * EMBc];
__device__ float  g_h1[Bc * 512];
__device__ float  g_h2[Bc * 256];

#define WT_OFF1 0
#define WT_OFF2 384
#define WT_OFF3 8576
#define WT_OFF4 24960
#define ST_OFF1 0
#define ST_OFF2 128
#define ST_OFF3 256
#define ST_OFF4 512
#define ST_OFF5 1024

// ---------------- double-float helpers ----------------
__device__ __forceinline__ void two_sum(float a, float b, float& s, float& e)
{
    s = __fadd_rn(a, b);
    float bp = __fsub_rn(s, a);
    e = __fadd_rn(__fsub_rn(a, __fsub_rn(s, bp)), __fsub_rn(b, bp));
}

__device__ __forceinline__ float2 dd_sub(float ah, float al, float2 b)
{
    float s1  = __fsub_rn(ah, b.x);
    float v   = __fsub_rn(s1, ah);
    float err = __fsub_rn(__fsub_rn(ah, __fsub_rn(s1, v)), __fadd_rn(b.x, v));
    err = __fadd_rn(err, __fsub_rn(al, b.y));
    float hi = __fadd_rn(s1, err);
    float lo = __fsub_rn(err, __fsub_rn(hi, s1));
    return make_float2(hi, lo);
}

// ---------------- kernels ----------------

// w1:(64,6) w2:(64,128) w3:(128,128) w4:(256,256)
__global__ void transpose_all(const float* __restrict__ w1, const float* __restrict__ w2,
                              const float* __restrict__ w3, const float* __restrict__ w4,
                              float* __restrict__ wT)
{
    int t = blockIdx.x * blockDim.x + threadIdx.x;
    const float* w; int O, C2, base, li;
    if (t < 384)        { w = w1; O = 64;  C2 = 6;   base = WT_OFF1; li = t; }
    else if (t < 8576)  { w = w2; O = 64;  C2 = 128; base = WT_OFF2; li = t - 384; }
    else if (t < 24960) { w = w3; O = 128; C2 = 128; base = WT_OFF3; li = t - 8576; }
    else if (t < 90496) { w = w4; O = 256; C2 = 256; base = WT_OFF4; li = t - 24960; }
    else return;
    int o = li / C2, c = li % C2;
    wT[base + c * O + o] = w[li];
}

__global__ void zerostats_kernel(double* __restrict__ stats)
{
    int t = blockIdx.x * blockDim.x + threadIdx.x;
    if (t < 3072) stats[t] = 0.0;
}

__global__ void xx_kernel(const float* __restrict__ x, float2* __restrict__ xx2, int C)
{
    int i = blockIdx.x * blockDim.x + threadIdx.x;
    if (i >= Bc * Nc) return;
    int b = i / Nc, n = i % Nc;
    double s = 0.0;
    for (int c = 0; c < C; c++) {
        double v = (double)x[((size_t)b * C + c) * Nc + n];
        s += v * v;
    }
    float hi = (float)s;
    float lo = (float)(s - (double)hi);
    xx2[i] = make_float2(hi, lo);
}

// fused dist + running top-20: computes each 64x64 dd pd tile with the EXACT same
// arithmetic chains as the old dist kernel, stages it in smem (two 32-col phases),
// and maintains per-row sorted top-20 lists (warp-owned rows, (val desc, idx asc)).
// Grid: (Nc/64 n-strips, MSPLIT m-splits, Bc). Partial lists merged by topkmerge.
__global__ void __launch_bounds__(256) disttopk_kernel(
    const float* __restrict__ x, const float2* __restrict__ xx2,
    float2* __restrict__ pv, int* __restrict__ pi, int C)
{
    __shared__ float  sn[8][64];
    __shared__ float  sm_[8][64];
    __shared__ float2 tile[64][32];
    __shared__ float2 lv[64][Kc];
    __shared__ int    li[64][Kc];
    __shared__ int    scnt[64];

    int b = blockIdx.z;
    int n0 = blockIdx.x * 64;
    int split = blockIdx.y;
    int t = threadIdx.x;
    int tx = t & 15, ty = t >> 4;
    int lane = t & 31, wid = t >> 5;
    const float* xb = x + (size_t)b * C * Nc;

    if (t < 64) scnt[t] = 0;
    __syncthreads();

    float2 xn[4];
#pragma unroll
    for (int i = 0; i < 4; i++) xn[i] = xx2[b * Nc + n0 + ty * 4 + i];

    for (int mt = 0; mt < Nc / (64 * MSPLIT); mt++) {
        int m0 = split * (Nc / MSPLIT) + mt * 64;

        // ---- compute 64x64 dd tile (bit-identical to prior dist kernel) ----
        u64 s2[4][2], e2[4][2];
#pragma unroll
        for (int i = 0; i < 4; i++)
#pragma unroll
            for (int jp = 0; jp < 2; jp++) { s2[i][jp] = 0ull; e2[i][jp] = 0ull; }

        for (int c0 = 0; c0 < C; c0 += 8) {
#pragma unroll
            for (int r = 0; r < 2; r++) {
                int ei = t + r * 256;
                int cc = ei >> 6, j = ei & 63;
                int c = c0 + cc;
                sn[cc][j]  = (c < C) ? xb[(size_t)c * Nc + n0 + j] : 0.f;
                sm_[cc][j] = (c < C) ? xb[(size_t)c * Nc + m0 + j] : 0.f;
            }
            __syncthreads();
            u64 f2[4][2];
#pragma unroll
            for (int i = 0; i < 4; i++) { f2[i][0] = 0ull; f2[i][1] = 0ull; }
#pragma unroll
            for (int q = 0; q < 8; q++) {
                float4 nv = *(const float4*)&sn[q][ty * 4];
                float4 mv = *(const float4*)&sm_[q][tx * 4];
                u64 m01 = pack2(mv.x, mv.y);
                u64 m23 = pack2(mv.z, mv.w);
                float nn[4] = {nv.x, nv.y, nv.z, nv.w};
#pragma unroll
                for (int i = 0; i < 4; i++) {
                    u64 np = pack2(nn[i], nn[i]);
                    f2[i][0] = fma2(np, m01, f2[i][0]);
                    f2[i][1] = fma2(np, m23, f2[i][1]);
                }
            }
#pragma unroll
            for (int i = 0; i < 4; i++)
#pragma unroll
                for (int jp = 0; jp < 2; jp++) {
                    u64 tt = add2(s2[i][jp], f2[i][jp]);
                    u64 bp = sub2(tt, s2[i][jp]);
                    u64 ea = sub2(s2[i][jp], sub2(tt, bp));
                    u64 eb = sub2(f2[i][jp], bp);
                    e2[i][jp] = add2(e2[i][jp], add2(ea, eb));
                    s2[i][jp] = tt;
                }
            __syncthreads();
        }

        float s[4][4], e[4][4];
#pragma unroll
        for (int i = 0; i < 4; i++) {
            unpack2(s2[i][0], s[i][0], s[i][1]);
            unpack2(s2[i][1], s[i][2], s[i][3]);
            unpack2(e2[i][0], e[i][0], e[i][1]);
            unpack2(e2[i][1], e[i][2], e[i][3]);
        }
        float2 xm[4];
#pragma unroll
        for (int j = 0; j < 4; j++) xm[j] = xx2[b * Nc + m0 + tx * 4 + j];
        float rx[4][4], ry[4][4];
#pragma unroll
        for (int i = 0; i < 4; i++)
#pragma unroll
            for (int j = 0; j < 4; j++) {
                float dh, dl;
                two_sum(s[i][j], e[i][j], dh, dl);
                dh = __fmul_rn(dh, 2.f);
                dl = __fmul_rn(dl, 2.f);
                float2 r1 = dd_sub(dh, dl, xn[i]);
                float2 r2 = dd_sub(r1.x, r1.y, xm[j]);
                rx[i][j] = r2.x; ry[i][j] = r2.y;
            }

        // ---- two 32-col phases: stage half-tile, scan into top-20 lists ----
#pragma unroll
        for (int ph = 0; ph < 2; ph++) {
            if ((tx >> 3) == ph) {
                int cb = tx * 4 - ph * 32;
#pragma unroll
                for (int i = 0; i < 4; i++)
#pragma unroll
                    for (int j = 0; j < 4; j++)
                        tile[ty * 4 + i][cb + j] = make_float2(rx[i][j], ry[i][j]);
            }
            __syncthreads();

            for (int r8 = 0; r8 < 8; r8++) {
                int r = wid * 8 + r8;
                int cnt = scnt[r];
                float2 v = tile[r][lane];
                int gi = m0 + ph * 32 + lane;
                bool done = false;
                while (true) {
                    bool qual;
                    if (cnt < Kc) qual = true;
                    else {
                        float2 tl = lv[r][Kc - 1];
                        int   tli = li[r][Kc - 1];
                        qual = (v.x > tl.x || (v.x == tl.x && (v.y > tl.y ||
                               (v.y == tl.y && gi < tli))));
                    }
                    unsigned bal = __ballot_sync(0xffffffffu, qual && !done);
                    if (!bal) break;
                    int src = __ffs(bal) - 1;
                    float cx = __shfl_sync(0xffffffffu, v.x, src);
                    float cy = __shfl_sync(0xffffffffu, v.y, src);
                    int  cgi = __shfl_sync(0xffffffffu, gi, src);
                    // warp-collective sorted insert
                    {
                        float ex = 0.f, ey = 0.f; int eidx = 0;
                        bool valid = lane < cnt;
                        if (valid) { float2 ee = lv[r][lane]; ex = ee.x; ey = ee.y; eidx = li[r][lane]; }
                        bool bet = valid && (ex > cx || (ex == cx && (ey > cy ||
                                   (ey == cy && eidx < cgi))));
                        unsigned bb = __ballot_sync(0xffffffffu, bet);
                        int pos = __popc(bb);
                        __syncwarp();
                        if (valid && lane >= pos && lane < Kc - 1) {
                            lv[r][lane + 1] = make_float2(ex, ey);
                            li[r][lane + 1] = eidx;
                        }
                        __syncwarp();
                        if (lane == pos) { lv[r][pos] = make_float2(cx, cy); li[r][pos] = cgi; }
                        __syncwarp();
                        if (cnt < Kc) cnt++;
                    }
                    if (lane == src) done = true;
                }
                scnt[r] = cnt;
            }
            __syncthreads();
        }
    }

    // write partial sorted lists
    for (int r8 = 0; r8 < 8; r8++) {
        int r = wid * 8 + r8;
        if (lane < Kc) {
            size_t base = (((size_t)b * Nc + n0 + r) * MSPLIT + split) * Kc + lane;
            pv[base] = lv[r][lane];
            pi[base] = li[r][lane];
        }
    }
}

// merge MSPLIT sorted partial top-20 lists per row (warp per row, 4-head merge)
__global__ void topkmerge_kernel(const float2* __restrict__ pv, const int* __restrict__ pi,
                                 int* __restrict__ idx)
{
    int row = blockIdx.x * 8 + (threadIdx.x >> 5);
    int lane = threadIdx.x & 31;
    size_t base = (size_t)row * (MSPLIT * Kc);
    bool act = lane < MSPLIT;
    int pos = 0;
    float hx = -INFINITY, hy = -INFINITY; int hidx = 0x7FFFFFFF;
    if (act) {
        float2 v = pv[base + lane * Kc];
        hx = v.x; hy = v.y; hidx = pi[base + lane * Kc];
    }
    int* out = idx + (size_t)row * Kc;
    for (int kk = 0; kk < Kc; kk++) {
        float bx = hx, by = hy; int bi = hidx, bl = lane;
#pragma unroll
        for (int off = 16; off; off >>= 1) {
            float ox = __shfl_xor_sync(0xffffffffu, bx, off);
            float oy = __shfl_xor_sync(0xffffffffu, by, off);
            int   oi = __shfl_xor_sync(0xffffffffu, bi, off);
            int   ol = __shfl_xor_sync(0xffffffffu, bl, off);
            if (ox > bx || (ox == bx && (oy > by || (oy == by && oi < bi)))) {
                bx = ox; by = oy; bi = oi; bl = ol;
            }
        }
        if (lane == 0) out[kk] = bi;
        if (lane == bl && act) {
            pos++;
            if (pos < Kc) {
                float2 v = pv[base + lane * Kc + pos];
                hx = v.x; hy = v.y; hidx = pi[base + lane * Kc + pos];
            } else { hx = -INFINITY; hy = -INFINITY; hidx = 0x7FFFFFFF; }
        }
    }
}

// fused edgeconv: G=2 n per block, LDS.128 feat loads, FFMA2 mainloop (bit-identical
// per-n chains), dd fp32 stat accumulation -> single fp64 atomic per channel pair.
__global__ void edgeconv_kernel(const float* __restrict__ xin, const float* __restrict__ wT,
                                const int* __restrict__ idx, float* __restrict__ ymax,
                                double* __restrict__ stats, int C, int O)
{
    extern __shared__ float shm[];
    int nA = blockIdx.x * 2, nB = nA + 1;
    int b = blockIdx.y, t = threadIdx.x;
    int C2 = 2 * C;
    float* featA = shm;
    float* featB = shm + C2 * Kc;
    float* ctrA  = featB + C2 * Kc;
    float* ctrB  = ctrA + C;
    int*   sidx  = (int*)(ctrB + C);

    if (t < Kc)          sidx[t]     = idx[((size_t)b * Nc + nA) * Kc + t];
    else if (t < 2 * Kc) sidx[t]     = idx[((size_t)b * Nc + nB) * Kc + (t - Kc)];
    for (int c = t; c < C; c += blockDim.x) {
        ctrA[c] = xin[((size_t)b * C + c) * Nc + nA];
        ctrB[c] = xin[((size_t)b * C + c) * Nc + nB];
    }
    __syncthreads();
    for (int e = t; e < C * Kc; e += blockDim.x) {
        int c = e / Kc, k = e - c * Kc;
        float cvA = ctrA[c], cvB = ctrB[c];
        float nvA = xin[((size_t)b * C + c) * Nc + sidx[k]];
        float nvB = xin[((size_t)b * C + c) * Nc + sidx[Kc + k]];
        featA[c * Kc + k]       = __fsub_rn(nvA, cvA);
        featA[(C + c) * Kc + k] = cvA;
        featB[c * Kc + k]       = __fsub_rn(nvB, cvB);
        featB[(C + c) * Kc + k] = cvB;
    }
    __syncthreads();

    u64 accA[Kc / 2], accB[Kc / 2];
#pragma unroll
    for (int p = 0; p < Kc / 2; p++) { accA[p] = 0ull; accB[p] = 0ull; }

#pragma unroll 2
    for (int c2 = 0; c2 < C2; c2++) {
        float w = wT[c2 * O + t];
        u64 wp = pack2(w, w);
        const ulonglong2* fA = reinterpret_cast<const ulonglong2*>(featA + c2 * Kc);
        const ulonglong2* fB = reinterpret_cast<const ulonglong2*>(featB + c2 * Kc);
#pragma unroll
        for (int p = 0; p < 5; p++) {
            ulonglong2 fa = fA[p];
            accA[2 * p]     = fma2(fa.x, wp, accA[2 * p]);
            accA[2 * p + 1] = fma2(fa.y, wp, accA[2 * p + 1]);
        }
#pragma unroll
        for (int p = 0; p < 5; p++) {
            ulonglong2 fb = fB[p];
            accB[2 * p]     = fma2(fb.x, wp, accB[2 * p]);
            accB[2 * p + 1] = fma2(fb.y, wp, accB[2 * p + 1]);
        }
    }

    float acc[Kc];
    double Stot = 0.0, Qtot = 0.0;
#pragma unroll
    for (int half = 0; half < 2; half++) {
        u64* a2 = half ? accB : accA;
#pragma unroll
        for (int p = 0; p < Kc / 2; p++) unpack2(a2[p], acc[2 * p], acc[2 * p + 1]);
        float m = acc[0];
        float s = 0.f, se = 0.f, q = 0.f, qe = 0.f;
#pragma unroll
        for (int k = 0; k < Kc; k++) {
            float a = acc[k];
            m = fmaxf(m, a);
            float th, te;
            two_sum(s, a, th, te);
            s = th; se = __fadd_rn(se, te);
            float ph = __fmul_rn(a, a);
            float pl = fmaf(a, a, -ph);
            two_sum(q, ph, th, te);
            q = th; qe = __fadd_rn(qe, __fadd_rn(te, pl));
        }
        int n = half ? nB : nA;
        ymax[((size_t)b * Nc + n) * O + t] = m;
        Stot += (double)s + (double)se;
        Qtot += (double)q + (double)qe;
    }
    atomicAdd(&stats[t], Stot);
    atomicAdd(&stats[O + t], Qtot);
}

// BN + lrelu on max-pooled values, smem-tile transpose [b][n][o] -> [b][o][n]
__global__ void bnapply_kernel(const float* __restrict__ ymax, const double* __restrict__ stats,
                               const float* __restrict__ g, const float* __restrict__ bta,
                               float* __restrict__ xout, int O, double invcnt)
{
    __shared__ float tile[32][33];
    int b  = blockIdx.z;
    int o0 = blockIdx.y * 32;
    int n0 = blockIdx.x * 32;
    int tx = threadIdx.x, ty = threadIdx.y;
    int o = o0 + tx;
    double mean = stats[o] * invcnt;
    double var  = stats[O + o] * invcnt - mean * mean;
    float m = (float)mean;
    float r = (float)rsqrt(var + EPSc);
    float gg = g[o], bb = bta[o];
#pragma unroll
    for (int rr = 0; rr < 4; rr++) {
        int n = n0 + ty + rr * 8;
        float vv = ymax[((size_t)b * Nc + n) * O + o];
        float y = __fadd_rn(__fmul_rn(__fmul_rn(__fsub_rn(vv, m), r), gg), bb);
        tile[ty + rr * 8][tx] = (y >= 0.f) ? y : SLOPEc * y;
    }
    __syncthreads();
#pragma unroll
    for (int rr = 0; rr < 4; rr++) {
        int oo = o0 + ty + rr * 8;
        xout[((size_t)b * O + oo) * Nc + n0 + tx] = tile[tx][ty + rr * 8];
    }
}

// conv5 with FFMA2 mainloop; dd per-thread stats -> fp64 smem/global atomics
__global__ void conv5_kernel(const float* __restrict__ w5,
                             const float* __restrict__ x1, const float* __restrict__ x2,
                             const float* __restrict__ x3, const float* __restrict__ x4,
                             float* __restrict__ z, double* __restrict__ stats)
{
    __shared__ float As[16][68];
    __shared__ float Bs[16][64];
    __shared__ double rs[64], rss[64];
    int b  = blockIdx.z;
    int o0 = blockIdx.y * 64;
    int n0 = blockIdx.x * 64;
    int t = threadIdx.x;
    int tx = t & 15, ty = t >> 4;
    u64 acc2[4][2];
#pragma unroll
    for (int i = 0; i < 4; i++) { acc2[i][0] = 0ull; acc2[i][1] = 0ull; }

    for (int c0 = 0; c0 < 512; c0 += 16) {
#pragma unroll
        for (int r = 0; r < 4; r++) {
            int e = t + r * 256;
            int oo = e >> 4, cc = e & 15;
            As[cc][oo] = w5[(size_t)(o0 + oo) * 512 + c0 + cc];
            int cc2 = e >> 6, jj = e & 63;
            int ch = c0 + cc2;
            const float* src; int cl, Cb;
            if (ch < 64)       { src = x1; cl = ch;       Cb = 64;  }
            else if (ch < 128) { src = x2; cl = ch - 64;  Cb = 64;  }
            else if (ch < 256) { src = x3; cl = ch - 128; Cb = 128; }
            else               { src = x4; cl = ch - 256; Cb = 256; }
            Bs[cc2][jj] = src[((size_t)b * Cb + cl) * Nc + n0 + jj];
        }
        __syncthreads();
#pragma unroll
        for (int cc = 0; cc < 16; cc++) {
            float4 av4 = *(const float4*)&As[cc][ty * 4];
            float4 bv4 = *(const float4*)&Bs[cc][tx * 4];
            u64 b01 = pack2(bv4.x, bv4.y);
            u64 b23 = pack2(bv4.z, bv4.w);
            float av[4] = {av4.x, av4.y, av4.z, av4.w};
#pragma unroll
            for (int i = 0; i < 4; i++) {
                u64 ap = pack2(av[i], av[i]);
                acc2[i][0] = fma2(ap, b01, acc2[i][0]);
                acc2[i][1] = fma2(ap, b23, acc2[i][1]);
            }
        }
        __syncthreads();
    }
    float acc[4][4];
#pragma unroll
    for (int i = 0; i < 4; i++) {
        unpack2(acc2[i][0], acc[i][0], acc[i][1]);
        unpack2(acc2[i][1], acc[i][2], acc[i][3]);
    }
    if (t < 64) { rs[t] = 0.0; rss[t] = 0.0; }
    __syncthreads();
#pragma unroll
    for (int i = 0; i < 4; i++) {
        int o = o0 + ty * 4 + i;
        float s = 0.f, se = 0.f, q = 0.f, qe = 0.f;
#pragma unroll
        for (int j = 0; j < 4; j++) {
            float a = acc[i][j];
            float th, te;
            two_sum(s, a, th, te);
            s = th; se = __fadd_rn(se, te);
            float ph = __fmul_rn(a, a);
            float pl = fmaf(a, a, -ph);
            two_sum(q, ph, th, te);
            q = th; qe = __fadd_rn(qe, __fadd_rn(te, pl));
        }
        atomicAdd(&rs[ty * 4 + i],  (double)s + (double)se);
        atomicAdd(&rss[ty * 4 + i], (double)q + (double)qe);
        float4 v4 = make_float4(acc[i][0], acc[i][1], acc[i][2], acc[i][3]);
        *reinterpret_cast<float4*>(&z[((size_t)b * EMBc + o) * Nc + n0 + tx * 4]) = v4;
    }
    __syncthreads();
    if (t < 64) {
        atomicAdd(&stats[o0 + t], rs[t]);
        atomicAdd(&stats[EMBc + o0 + t], rss[t]);
    }
}

__global__ void pool5_kernel(const float* __restrict__ z, const double* __restrict__ stats,
                             const float* __restrict__ g, const float* __restrict__ bta,
                             float* __restrict__ p)
{
    int o = blockIdx.x, b = blockIdx.y, lane = threadIdx.x;
    const double inv = 1.0 / (double)(Bc * Nc);
    double mean = stats[o] * inv;
    double var  = stats[EMBc + o] * inv - mean * mean;
    float m = (float)mean;
    float r = (float)rsqrt(var + EPSc);
    float gg = g[o], bb = bta[o];
    const float* row = z + ((size_t)b * EMBc + o) * Nc;
    float mx = -INFINITY, sm = 0.f;
    for (int j = lane; j < Nc; j += 32) {
        float v = __fadd_rn(__fmul_rn(__fmul_rn(__fsub_rn(row[j], m), r), gg), bb);
        v = (v >= 0.f) ? v : SLOPEc * v;
        mx = fmaxf(mx, v);
        sm += v;
    }
    for (int off = 16; off; off >>= 1) {
        mx = fmaxf(mx, __shfl_xor_sync(0xffffffffu, mx, off));
        sm += __shfl_xor_sync(0xffffffffu, sm, off);
    }
    if (lane == 0) {
        p[b * 2 * EMBc + o] = mx;
        p[b * 2 * EMBc + EMBc + o] = sm * (1.0f / Nc);
    }
}

__global__ void fc_bn_kernel(const float* __restrict__ in, const float* __restrict__ W,
                             const float* __restrict__ bias, const float* __restrict__ g,
                             const float* __restrict__ bta, float* __restrict__ out,
                             int Cin, int Cout)
{
    int j = blockIdx.x, t = threadIdx.x;
    float a[Bc];
#pragma unroll
    for (int b_ = 0; b_ < Bc; b_++) a[b_] = 0.f;
    for (int e = t; e < Cin; e += 64) {
        float w = W[(size_t)j * Cin + e];
#pragma unroll
        for (int b_ = 0; b_ < Bc; b_++) a[b_] = fmaf(w, in[b_ * Cin + e], a[b_]);
    }
    __shared__ float red[64][Bc];
#pragma unroll
    for (int b_ = 0; b_ < Bc; b_++) red[t][b_] = a[b_];
    __syncthreads();
    for (int s = 32; s > 0; s >>= 1) {
        if (t < s) {
#pragma unroll
            for (int b_ = 0; b_ < Bc; b_++) red[t][b_] += red[t + s][b_];
        }
        __syncthreads();
    }
    if (t < Bc) {
        float bb = bias ? bias[j] : 0.f;
        float vals[Bc];
        double mean = 0.0;
#pragma unroll
        for (int b_ = 0; b_ < Bc; b_++) { vals[b_] = red[0][b_] + bb; mean += (double)vals[b_]; }
        mean *= (1.0 / Bc);
        double var = 0.0;
#pragma unroll
        for (int b_ = 0; b_ < Bc; b_++) { double d = (double)vals[b_] - mean; var += d * d; }
        var *= (1.0 / Bc);
        float m = (float)mean;
        float r = (float)rsqrt(var + EPSc);
        float y = __fadd_rn(__fmul_rn(__fmul_rn(__fsub_rn(vals[t], m), r), g[j]), bta[j]);
        out[t * Cout + j] = (y >= 0.f) ? y : SLOPEc * y;
    }
}

__global__ void fc3_kernel(const float* __restrict__ in, const float* __restrict__ W,
                           const float* __restrict__ bias, float* __restrict__ out)
{
    int t = threadIdx.x;
    if (t >= Bc * 40) return;
    int b = t / 40, j = t % 40;
    float s = 0.f;
    for (int e = 0; e < 256; e++) s = fmaf(W[j * 256 + e], in[b * 256 + e], s);
    out[t] = __fadd_rn(s, bias[j]);
}

// ---------------- host orchestration ----------------

static void run_edge_block(const float* xin, int C, int O,
                           const float* wTseg, const float* g, const float* bta,
                           float* xout,
                           float2* pv, int* pi, float2* xxp, int* idxp,
                           float* ymax, double* statseg)
{
    xx_kernel<<<(Bc * Nc + 255) / 256, 256>>>(xin, xxp, C);
    disttopk_kernel<<<dim3(Nc / 64, MSPLIT, Bc), 256>>>(xin, xxp, pv, pi, C);
    topkmerge_kernel<<<Bc * Nc / 8, 256>>>(pv, pi, idxp);
    size_t shm = (size_t)(2 * (2 * C * Kc + C)) * sizeof(float) + 2 * Kc * sizeof(int);
    edgeconv_kernel<<<dim3(Nc / 2, Bc), O, shm>>>(xin, wTseg, idxp, ymax, statseg, C, O);
    bnapply_kernel<<<dim3(Nc / 32, O / 32, Bc), dim3(32, 8)>>>(ymax, statseg, g, bta, xout, O,
                                                               1.0 / (double)(Bc * Nc * Kc));
}

extern "C" void kernel_launch(void* const* d_in, const int* in_sizes, int n_in,
                              void* d_out, int out_size)
{
    const float* x   = (const float*)d_in[0];
    const float* w1  = (const float*)d_in[1];
    const float* w2  = (const float*)d_in[2];
    const float* w3  = (const float*)d_in[3];
    const float* w4  = (const float*)d_in[4];
    const float* w5  = (const float*)d_in[5];
    const float* lw1 = (const float*)d_in[6];
    const float* lw2 = (const float*)d_in[7];
    const float* lb2 = (const float*)d_in[8];
    const float* lw3 = (const float*)d_in[9];
    const float* lb3 = (const float*)d_in[10];
    const float* g1 = (const float*)d_in[11]; const float* b1 = (const float*)d_in[12];
    const float* g2 = (const float*)d_in[13]; const float* b2 = (const float*)d_in[14];
    const float* g3 = (const float*)d_in[15]; const float* b3 = (const float*)d_in[16];
    const float* g4 = (const float*)d_in[17]; const float* b4 = (const float*)d_in[18];
    const float* g5 = (const float*)d_in[19]; const float* b5 = (const float*)d_in[20];
    const float* g6 = (const float*)d_in[21]; const float* b6 = (const float*)d_in[22];
    const float* g7 = (const float*)d_in[23]; const float* b7 = (const float*)d_in[24];

    float *wT, *ymax, *x1b, *x2b, *x3b, *x4b, *z5, *pbuf, *h1, *h2;
    float2 *pv, *xxp;
    double* stats;
    int *idxp, *pi;
    cudaGetSymbolAddress((void**)&pv,    g_pv);
    cudaGetSymbolAddress((void**)&pi,    g_pi);
    cudaGetSymbolAddress((void**)&xxp,   g_xx2);
    cudaGetSymbolAddress((void**)&idxp,  g_idx);
    cudaGetSymbolAddress((void**)&wT,    g_wT);
    cudaGetSymbolAddress((void**)&ymax,  g_ymax);
    cudaGetSymbolAddress((void**)&stats, g_statsd);
    cudaGetSymbolAddress((void**)&x1b,   g_x1);
    cudaGetSymbolAddress((void**)&x2b,   g_x2);
    cudaGetSymbolAddress((void**)&x3b,   g_x3);
    cudaGetSymbolAddress((void**)&x4b,   g_x4);
    cudaGetSymbolAddress((void**)&z5,    g_z5);
    cudaGetSymbolAddress((void**)&pbuf,  g_p);
    cudaGetSymbolAddress((void**)&h1,    g_h1);
    cudaGetSymbolAddress((void**)&h2,    g_h2);

    transpose_all<<<(90496 + 255) / 256, 256>>>(w1, w2, w3, w4, wT);
    zerostats_kernel<<<12, 256>>>(stats);

    run_edge_block(x,   3,   64,  wT + WT_OFF1, g1, b1, x1b, pv, pi, xxp, idxp, ymax, stats + ST_OFF1);
    run_edge_block(x1b, 64,  64,  wT + WT_OFF2, g2, b2, x2b, pv, pi, xxp, idxp, ymax, stats + ST_OFF2);
    run_edge_block(x2b, 64,  128, wT + WT_OFF3, g3, b3, x3b, pv, pi, xxp, idxp, ymax, stats + ST_OFF3);
    run_edge_block(x3b, 128, 256, wT + WT_OFF4, g4, b4, x4b, pv, pi, xxp, idxp, ymax, stats + ST_OFF4);

    conv5_kernel<<<dim3(Nc / 64, EMBc / 64, Bc), 256>>>(w5, x1b, x2b, x3b, x4b, z5, stats + ST_OFF5);
    pool5_kernel<<<dim3(EMBc, Bc), 32>>>(z5, stats + ST_OFF5, g5, b5, pbuf);

    fc_bn_kernel<<<512, 64>>>(pbuf, lw1, nullptr, g6, b6, h1, 2 * EMBc, 512);
    fc_bn_kernel<<<256, 64>>>(h1, lw2, lb2, g7, b7, h2, 512, 256);
    fc3_kernel<<<1, 320>>>(h2, lw3, lb3, (float*)d_out);
}

// round 13
// speedup vs baseline: 1.2526x; 1.2526x over previous
#include <cuda_runtime.h>
#include <cstdint>
#include <math.h>

#define Bc 8
#define Nc 2048
#define Kc 20
#define EMBc 1024
#define EPSc 1e-5
#define SLOPEc 0.2f

typedef unsigned long long u64;

// ---------------- packed f32x2 helpers (exact dual IEEE fp32 ops) ----------------
__device__ __forceinline__ u64 pack2(float lo, float hi)
{
    u64 r; asm("mov.b64 %0, {%1, %2};" : "=l"(r) : "f"(lo), "f"(hi)); return r;
}
__device__ __forceinline__ void unpack2(u64 v, float& lo, float& hi)
{
    asm("mov.b64 {%0, %1}, %2;" : "=f"(lo), "=f"(hi) : "l"(v));
}
__device__ __forceinline__ u64 fma2(u64 a, u64 b, u64 c)
{
    u64 d; asm("fma.rn.f32x2 %0, %1, %2, %3;" : "=l"(d) : "l"(a), "l"(b), "l"(c)); return d;
}
__device__ __forceinline__ u64 add2(u64 a, u64 b)
{
    u64 d; asm("add.rn.f32x2 %0, %1, %2;" : "=l"(d) : "l"(a), "l"(b)); return d;
}
__device__ __forceinline__ u64 sub2(u64 a, u64 b)
{
    return fma2(b, 0xBF800000BF800000ull, a);
}

// ---------------- scratch ----------------
__device__ float2 g_dist2[(size_t)Bc * Nc * Nc];
__device__ float2 g_xx2[Bc * Nc];
__device__ int    g_idx[Bc * Nc * Kc];
__device__ float  g_x1[Bc * 64 * Nc];
__device__ float  g_x2[Bc * 64 * Nc];
__device__ float  g_x3[Bc * 128 * Nc];
__device__ float  g_x4[Bc * 256 * Nc];
__device__ float  g_wT[90496];
__device__ float  g_ymax[Bc * Nc * 256];
__device__ double g_statsd[3072];
__device__ float  g_z5[Bc * EMBc * Nc];
__device__ float  g_p[Bc * 2 * EMBc];
__device__ float  g_h1[Bc * 512];
__device__ float  g_h2[Bc * 256];

#define WT_OFF1 0
#define WT_OFF2 384
#define WT_OFF3 8576
#define WT_OFF4 24960
#define ST_OFF1 0
#define ST_OFF2 128
#define ST_OFF3 256
#define ST_OFF4 512
#define ST_OFF5 1024

// ---------------- double-float helpers ----------------
__device__ __forceinline__ void two_sum(float a, float b, float& s, float& e)
{
    s = __fadd_rn(a, b);
    float bp = __fsub_rn(s, a);
    e = __fadd_rn(__fsub_rn(a, __fsub_rn(s, bp)), __fsub_rn(b, bp));
}

__device__ __forceinline__ float2 dd_sub(float ah, float al, float2 b)
{
    float s1  = __fsub_rn(ah, b.x);
    float v   = __fsub_rn(s1, ah);
    float err = __fsub_rn(__fsub_rn(ah, __fsub_rn(s1, v)), __fadd_rn(b.x, v));
    err = __fadd_rn(err, __fsub_rn(al, b.y));
    float hi = __fadd_rn(s1, err);
    float lo = __fsub_rn(err, __fsub_rn(hi, s1));
    return make_float2(hi, lo);
}

__device__ __forceinline__ bool dd_gt(float2 a, float2 b)
{
    return (a.x > b.x) || (a.x == b.x && a.y > b.y);
}

// ---------------- kernels ----------------

// w1:(64,6) w2:(64,128) w3:(128,128) w4:(256,256)
__global__ void transpose_all(const float* __restrict__ w1, const float* __restrict__ w2,
                              const float* __restrict__ w3, const float* __restrict__ w4,
                              float* __restrict__ wT)
{
    int t = blockIdx.x * blockDim.x + threadIdx.x;
    const float* w; int O, C2, base, li;
    if (t < 384)        { w = w1; O = 64;  C2 = 6;   base = WT_OFF1; li = t; }
    else if (t < 8576)  { w = w2; O = 64;  C2 = 128; base = WT_OFF2; li = t - 384; }
    else if (t < 24960) { w = w3; O = 128; C2 = 128; base = WT_OFF3; li = t - 8576; }
    else if (t < 90496) { w = w4; O = 256; C2 = 256; base = WT_OFF4; li = t - 24960; }
    else return;
    int o = li / C2, c = li % C2;
    wT[base + c * O + o] = w[li];
}

__global__ void zerostats_kernel(double* __restrict__ stats)
{
    int t = blockIdx.x * blockDim.x + threadIdx.x;
    if (t < 3072) stats[t] = 0.0;
}

__global__ void xx_kernel(const float* __restrict__ x, float2* __restrict__ xx2, int C)
{
    int i = blockIdx.x * blockDim.x + threadIdx.x;
    if (i >= Bc * Nc) return;
    int b = i / Nc, n = i % Nc;
    double s = 0.0;
    for (int c = 0; c < C; c++) {
        double v = (double)x[((size_t)b * C + c) * Nc + n];
        s += v * v;
    }
    float hi = (float)s;
    float lo = (float)(s - (double)hi);
    xx2[i] = make_float2(hi, lo);
}

// pd = 2*dot - xx_n - xx_m as double-float (bit-exact chain, unchanged)
__global__ void dist_kernel(const float* __restrict__ x, const float2* __restrict__ xx2,
                            float2* __restrict__ dist, int C)
{
    __shared__ float sn[8][64];
    __shared__ float sm_[8][64];
    int b = blockIdx.z;
    int n0 = blockIdx.y * 64, m0 = blockIdx.x * 64;
    int t = threadIdx.x;
    int tx = t & 15, ty = t >> 4;
    u64 s2[4][2], e2[4][2];
#pragma unroll
    for (int i = 0; i < 4; i++)
#pragma unroll
        for (int jp = 0; jp < 2; jp++) { s2[i][jp] = 0ull; e2[i][jp] = 0ull; }
    const float* xb = x + (size_t)b * C * Nc;

    for (int c0 = 0; c0 < C; c0 += 8) {
#pragma unroll
        for (int r = 0; r < 2; r++) {
            int ei = t + r * 256;
            int cc = ei >> 6, j = ei & 63;
            int c = c0 + cc;
            sn[cc][j]  = (c < C) ? xb[(size_t)c * Nc + n0 + j] : 0.f;
            sm_[cc][j] = (c < C) ? xb[(size_t)c * Nc + m0 + j] : 0.f;
        }
        __syncthreads();
        u64 f2[4][2];
#pragma unroll
        for (int i = 0; i < 4; i++) { f2[i][0] = 0ull; f2[i][1] = 0ull; }
#pragma unroll
        for (int q = 0; q < 8; q++) {
            float4 nv = *(const float4*)&sn[q][ty * 4];
            float4 mv = *(const float4*)&sm_[q][tx * 4];
            u64 m01 = pack2(mv.x, mv.y);
            u64 m23 = pack2(mv.z, mv.w);
            float nn[4] = {nv.x, nv.y, nv.z, nv.w};
#pragma unroll
            for (int i = 0; i < 4; i++) {
                u64 np = pack2(nn[i], nn[i]);
                f2[i][0] = fma2(np, m01, f2[i][0]);
                f2[i][1] = fma2(np, m23, f2[i][1]);
            }
        }
#pragma unroll
        for (int i = 0; i < 4; i++)
#pragma unroll
            for (int jp = 0; jp < 2; jp++) {
                u64 tt = add2(s2[i][jp], f2[i][jp]);
                u64 bp = sub2(tt, s2[i][jp]);
                u64 ea = sub2(s2[i][jp], sub2(tt, bp));
                u64 eb = sub2(f2[i][jp], bp);
                e2[i][jp] = add2(e2[i][jp], add2(ea, eb));
                s2[i][jp] = tt;
            }
        __syncthreads();
    }
    int n = n0 + ty * 4, m = m0 + tx * 4;
    float s[4][4], e[4][4];
#pragma unroll
    for (int i = 0; i < 4; i++) {
        unpack2(s2[i][0], s[i][0], s[i][1]);
        unpack2(s2[i][1], s[i][2], s[i][3]);
        unpack2(e2[i][0], e[i][0], e[i][1]);
        unpack2(e2[i][1], e[i][2], e[i][3]);
    }
    float2 xn[4], xm[4];
#pragma unroll
    for (int i = 0; i < 4; i++) { xn[i] = xx2[b * Nc + n + i]; xm[i] = xx2[b * Nc + m + i]; }
    float2* dr = dist + (size_t)b * Nc * Nc;
#pragma unroll
    for (int i = 0; i < 4; i++)
#pragma unroll
        for (int j = 0; j < 4; j++) {
            float dh, dl;
            two_sum(s[i][j], e[i][j], dh, dl);
            dh = __fmul_rn(dh, 2.f);
            dl = __fmul_rn(dl, 2.f);
            float2 r1 = dd_sub(dh, dl, xn[i]);
            float2 r2 = dd_sub(r1.x, r1.y, xm[j]);
            dr[(size_t)(n + i) * Nc + m + j] = r2;
        }
}

// merge-based top-20 (R11-proven): per-thread Batcher sort of 8 keys, shuffle-only
// warp merge, warp-0 merges the 8 per-warp lists. Order: (val desc, idx asc).
#define CE(i, j) { \
    bool sw = (vx[j] > vx[i]) || (vx[j] == vx[i] && (vy[j] > vy[i] || (vy[j] == vy[i] && vi[j] < vi[i]))); \
    if (sw) { float tx_ = vx[i]; vx[i] = vx[j]; vx[j] = tx_; \
              float ty_ = vy[i]; vy[i] = vy[j]; vy[j] = ty_; \
              int   ti_ = vi[i]; vi[i] = vi[j]; vi[j] = ti_; } }

__global__ void topk_kernel(const float2* __restrict__ dist, int* __restrict__ idx)
{
    int row = blockIdx.x;
    int t = threadIdx.x;
    int lane = t & 31, wid = t >> 5;
    const float4* d4 = (const float4*)(dist + (size_t)row * Nc) + t * 4;
    float vx[8], vy[8];
    int vi[8];
#pragma unroll
    for (int q = 0; q < 4; q++) {
        float4 f = d4[q];
        vx[2 * q]     = f.x; vy[2 * q]     = f.y;
        vx[2 * q + 1] = f.z; vy[2 * q + 1] = f.w;
        vi[2 * q]     = t * 8 + 2 * q;
        vi[2 * q + 1] = t * 8 + 2 * q + 1;
    }
    CE(0,1) CE(2,3) CE(4,5) CE(6,7)
    CE(0,2) CE(1,3) CE(4,6) CE(5,7)
    CE(1,2) CE(5,6)
    CE(0,4) CE(1,5) CE(2,6) CE(3,7)
    CE(2,4) CE(3,5)
    CE(1,2) CE(3,4) CE(5,6)

    __shared__ float swx[8][Kc], swy[8][Kc];
    __shared__ int   swi[8][Kc];

    for (int kk = 0; kk < Kc; kk++) {
        float bx = vx[0], by = vy[0];
        int bi = vi[0], bl = lane;
#pragma unroll
        for (int off = 16; off; off >>= 1) {
            float ox = __shfl_xor_sync(0xffffffffu, bx, off);
            float oy = __shfl_xor_sync(0xffffffffu, by, off);
            int   oi = __shfl_xor_sync(0xffffffffu, bi, off);
            int   ol = __shfl_xor_sync(0xffffffffu, bl, off);
            if (ox > bx || (ox == bx && (oy > by || (oy == by && oi < bi)))) {
                bx = ox; by = oy; bi = oi; bl = ol;
            }
        }
        if (lane == 0) { swx[wid][kk] = bx; swy[wid][kk] = by; swi[wid][kk] = bi; }
        if (lane == bl) {
#pragma unroll
            for (int q = 0; q < 7; q++) { vx[q] = vx[q + 1]; vy[q] = vy[q + 1]; vi[q] = vi[q + 1]; }
            vx[7] = -INFINITY; vy[7] = -INFINITY; vi[7] = 0x7FFFFFFF;
        }
    }
    __syncthreads();

    if (t < 32) {
        bool act = lane < 8;
        int pos = 0;
        float hx = act ? swx[lane][0] : -INFINITY;
        float hy = act ? swy[lane][0] : -INFINITY;
        int   hidx = act ? swi[lane][0] : 0x7FFFFFFF;
        int* out = idx + (size_t)row * Kc;
        for (int kk = 0; kk < Kc; kk++) {
            float bx = hx, by = hy;
            int bi = hidx, bl = lane;
#pragma unroll
            for (int off = 16; off; off >>= 1) {
                float ox = __shfl_xor_sync(0xffffffffu, bx, off);
                float oy = __shfl_xor_sync(0xffffffffu, by, off);
                int   oi = __shfl_xor_sync(0xffffffffu, bi, off);
                int   ol = __shfl_xor_sync(0xffffffffu, bl, off);
                if (ox > bx || (ox == bx && (oy > by || (oy == by && oi < bi)))) {
                    bx = ox; by = oy; bi = oi; bl = ol;
                }
            }
            if (lane == 0) out[kk] = bi;
            if (lane == bl) {
                pos++;
                if (pos < Kc) { hx = swx[lane][pos]; hy = swy[lane][pos]; hidx = swi[lane][pos]; }
                else          { hx = -INFINITY; hy = -INFINITY; hidx = 0x7FFFFFFF; }
            }
        }
    }
}

// fused edgeconv: G=2 n per block, LDS.128 feat loads, FFMA2 mainloop (bit-identical
// per-n chains), dd fp32 stat accumulation -> single fp64 atomic per channel pair.
__global__ void edgeconv_kernel(const float* __restrict__ xin, const float* __restrict__ wT,
                                const int* __restrict__ idx, float* __restrict__ ymax,
                                double* __restrict__ stats, int C, int O)
{
    extern __shared__ float shm[];
    int nA = blockIdx.x * 2, nB = nA + 1;
    int b = blockIdx.y, t = threadIdx.x;
    int C2 = 2 * C;
    float* featA = shm;
    float* featB = shm + C2 * Kc;
    float* ctrA  = featB + C2 * Kc;
    float* ctrB  = ctrA + C;
    int*   sidx  = (int*)(ctrB + C);

    if (t < Kc)          sidx[t]     = idx[((size_t)b * Nc + nA) * Kc + t];
    else if (t < 2 * Kc) sidx[t]     = idx[((size_t)b * Nc + nB) * Kc + (t - Kc)];
    for (int c = t; c < C; c += blockDim.x) {
        ctrA[c] = xin[((size_t)b * C + c) * Nc + nA];
        ctrB[c] = xin[((size_t)b * C + c) * Nc + nB];
    }
    __syncthreads();
    for (int e = t; e < C * Kc; e += blockDim.x) {
        int c = e / Kc, k = e - c * Kc;
        float cvA = ctrA[c], cvB = ctrB[c];
        float nvA = xin[((size_t)b * C + c) * Nc + sidx[k]];
        float nvB = xin[((size_t)b * C + c) * Nc + sidx[Kc + k]];
        featA[c * Kc + k]       = __fsub_rn(nvA, cvA);
        featA[(C + c) * Kc + k] = cvA;
        featB[c * Kc + k]       = __fsub_rn(nvB, cvB);
        featB[(C + c) * Kc + k] = cvB;
    }
    __syncthreads();

    u64 accA[Kc / 2], accB[Kc / 2];
#pragma unroll
    for (int p = 0; p < Kc / 2; p++) { accA[p] = 0ull; accB[p] = 0ull; }

    const float* wptr = wT + t;
#pragma unroll 2
    for (int c2 = 0; c2 < C2; c2++) {
        float w = __ldg(wptr + c2 * O);
        u64 wp = pack2(w, w);
        const ulonglong2* fA = reinterpret_cast<const ulonglong2*>(featA + c2 * Kc);
        const ulonglong2* fB = reinterpret_cast<const ulonglong2*>(featB + c2 * Kc);
#pragma unroll
        for (int p = 0; p < 5; p++) {
            ulonglong2 fa = fA[p];
            accA[2 * p]     = fma2(fa.x, wp, accA[2 * p]);
            accA[2 * p + 1] = fma2(fa.y, wp, accA[2 * p + 1]);
        }
#pragma unroll
        for (int p = 0; p < 5; p++) {
            ulonglong2 fb = fB[p];
            accB[2 * p]     = fma2(fb.x, wp, accB[2 * p]);
            accB[2 * p + 1] = fma2(fb.y, wp, accB[2 * p + 1]);
        }
    }

    float acc[Kc];
    double Stot = 0.0, Qtot = 0.0;
#pragma unroll
    for (int half = 0; half < 2; half++) {
        u64* a2 = half ? accB : accA;
#pragma unroll
        for (int p = 0; p < Kc / 2; p++) unpack2(a2[p], acc[2 * p], acc[2 * p + 1]);
        float m = acc[0];
        float s = 0.f, se = 0.f, q = 0.f, qe = 0.f;
#pragma unroll
        for (int k = 0; k < Kc; k++) {
            float a = acc[k];
            m = fmaxf(m, a);
            float th, te;
            two_sum(s, a, th, te);
            s = th; se = __fadd_rn(se, te);
            float ph = __fmul_rn(a, a);
            float pl = fmaf(a, a, -ph);
            two_sum(q, ph, th, te);
            q = th; qe = __fadd_rn(qe, __fadd_rn(te, pl));
        }
        int n = half ? nB : nA;
        ymax[((size_t)b * Nc + n) * O + t] = m;
        Stot += (double)s + (double)se;
        Qtot += (double)q + (double)qe;
    }
    atomicAdd(&stats[t], Stot);
    atomicAdd(&stats[O + t], Qtot);
}

// BN + lrelu on max-pooled values, smem-tile transpose [b][n][o] -> [b][o][n]
__global__ void bnapply_kernel(const float* __restrict__ ymax, const double* __restrict__ stats,
                               const float* __restrict__ g, const float* __restrict__ bta,
                               float* __restrict__ xout, int O, double invcnt)
{
    __shared__ float tile[32][33];
    int b  = blockIdx.z;
    int o0 = blockIdx.y * 32;
    int n0 = blockIdx.x * 32;
    int tx = threadIdx.x, ty = threadIdx.y;
    int o = o0 + tx;
    double mean = stats[o] * invcnt;
    double var  = stats[O + o] * invcnt - mean * mean;
    float m = (float)mean;
    float r = (float)rsqrt(var + EPSc);
    float gg = g[o], bb = bta[o];
#pragma unroll
    for (int rr = 0; rr < 4; rr++) {
        int n = n0 + ty + rr * 8;
        float vv = ymax[((size_t)b * Nc + n) * O + o];
        float y = __fadd_rn(__fmul_rn(__fmul_rn(__fsub_rn(vv, m), r), gg), bb);
        tile[ty + rr * 8][tx] = (y >= 0.f) ? y : SLOPEc * y;
    }
    __syncthreads();
#pragma unroll
    for (int rr = 0; rr < 4; rr++) {
        int oo = o0 + ty + rr * 8;
        xout[((size_t)b * O + oo) * Nc + n0 + tx] = tile[tx][ty + rr * 8];
    }
}

// conv5 with FFMA2 mainloop; dd per-thread stats -> fp64 smem/global atomics
__global__ void conv5_kernel(const float* __restrict__ w5,
                             const float* __restrict__ x1, const float* __restrict__ x2,
                             const float* __restrict__ x3, const float* __restrict__ x4,
                             float* __restrict__ z, double* __restrict__ stats)
{
    __shared__ float As[16][68];
    __shared__ float Bs[16][64];
    __shared__ double rs[64], rss[64];
    int b  = blockIdx.z;
    int o0 = blockIdx.y * 64;
    int n0 = blockIdx.x * 64;
    int t = threadIdx.x;
    int tx = t & 15, ty = t >> 4;
    u64 acc2[4][2];
#pragma unroll
    for (int i = 0; i < 4; i++) { acc2[i][0] = 0ull; acc2[i][1] = 0ull; }

    for (int c0 = 0; c0 < 512; c0 += 16) {
#pragma unroll
        for (int r = 0; r < 4; r++) {
            int e = t + r * 256;
            int oo = e >> 4, cc = e & 15;
            As[cc][oo] = w5[(size_t)(o0 + oo) * 512 + c0 + cc];
            int cc2 = e >> 6, jj = e & 63;
            int ch = c0 + cc2;
            const float* src; int cl, Cb;
            if (ch < 64)       { src = x1; cl = ch;       Cb = 64;  }
            else if (ch < 128) { src = x2; cl = ch - 64;  Cb = 64;  }
            else if (ch < 256) { src = x3; cl = ch - 128; Cb = 128; }
            else               { src = x4; cl = ch - 256; Cb = 256; }
            Bs[cc2][jj] = src[((size_t)b * Cb + cl) * Nc + n0 + jj];
        }
        __syncthreads();
#pragma unroll
        for (int cc = 0; cc < 16; cc++) {
            float4 av4 = *(const float4*)&As[cc][ty * 4];
            float4 bv4 = *(const float4*)&Bs[cc][tx * 4];
            u64 b01 = pack2(bv4.x, bv4.y);
            u64 b23 = pack2(bv4.z, bv4.w);
            float av[4] = {av4.x, av4.y, av4.z, av4.w};
#pragma unroll
            for (int i = 0; i < 4; i++) {
                u64 ap = pack2(av[i], av[i]);
                acc2[i][0] = fma2(ap, b01, acc2[i][0]);
                acc2[i][1] = fma2(ap, b23, acc2[i][1]);
            }
        }
        __syncthreads();
    }
    float acc[4][4];
#pragma unroll
    for (int i = 0; i < 4; i++) {
        unpack2(acc2[i][0], acc[i][0], acc[i][1]);
        unpack2(acc2[i][1], acc[i][2], acc[i][3]);
    }
    if (t < 64) { rs[t] = 0.0; rss[t] = 0.0; }
    __syncthreads();
#pragma unroll
    for (int i = 0; i < 4; i++) {
        int o = o0 + ty * 4 + i;
        float s = 0.f, se = 0.f, q = 0.f, qe = 0.f;
#pragma unroll
        for (int j = 0; j < 4; j++) {
            float a = acc[i][j];
            float th, te;
            two_sum(s, a, th, te);
            s = th; se = __fadd_rn(se, te);
            float ph = __fmul_rn(a, a);
            float pl = fmaf(a, a, -ph);
            two_sum(q, ph, th, te);
            q = th; qe = __fadd_rn(qe, __fadd_rn(te, pl));
        }
        atomicAdd(&rs[ty * 4 + i],  (double)s + (double)se);
        atomicAdd(&rss[ty * 4 + i], (double)q + (double)qe);
        float4 v4 = make_float4(acc[i][0], acc[i][1], acc[i][2], acc[i][3]);
        *reinterpret_cast<float4*>(&z[((size_t)b * EMBc + o) * Nc + n0 + tx * 4]) = v4;
    }
    __syncthreads();
    if (t < 64) {
        atomicAdd(&stats[o0 + t], rs[t]);
        atomicAdd(&stats[EMBc + o0 + t], rss[t]);
    }
}

__global__ void pool5_kernel(const float* __restrict__ z, const double* __restrict__ stats,
                             const float* __restrict__ g, const float* __restrict__ bta,
                             float* __restrict__ p)
{
    int o = blockIdx.x, b = blockIdx.y, lane = threadIdx.x;
    const double inv = 1.0 / (double)(Bc * Nc);
    double mean = stats[o] * inv;
    double var  = stats[EMBc + o] * inv - mean * mean;
    float m = (float)mean;
    float r = (float)rsqrt(var + EPSc);
    float gg = g[o], bb = bta[o];
    const float* row = z + ((size_t)b * EMBc + o) * Nc;
    float mx = -INFINITY, sm = 0.f;
    for (int j = lane; j < Nc; j += 32) {
        float v = __fadd_rn(__fmul_rn(__fmul_rn(__fsub_rn(row[j], m), r), gg), bb);
        v = (v >= 0.f) ? v : SLOPEc * v;
        mx = fmaxf(mx, v);
        sm += v;
    }
    for (int off = 16; off; off >>= 1) {
        mx = fmaxf(mx, __shfl_xor_sync(0xffffffffu, mx, off));
        sm += __shfl_xor_sync(0xffffffffu, sm, off);
    }
    if (lane == 0) {
        p[b * 2 * EMBc + o] = mx;
        p[b * 2 * EMBc + EMBc + o] = sm * (1.0f / Nc);
    }
}

__global__ void fc_bn_kernel(const float* __restrict__ in, const float* __restrict__ W,
                             const float* __restrict__ bias, const float* __restrict__ g,
                             const float* __restrict__ bta, float* __restrict__ out,
                             int Cin, int Cout)
{
    int j = blockIdx.x, t = threadIdx.x;
    float a[Bc];
#pragma unroll
    for (int b_ = 0; b_ < Bc; b_++) a[b_] = 0.f;
    for (int e = t; e < Cin; e += 64) {
        float w = W[(size_t)j * Cin + e];
#pragma unroll
        for (int b_ = 0; b_ < Bc; b_++) a[b_] = fmaf(w, in[b_ * Cin + e], a[b_]);
    }
    __shared__ float red[64][Bc];
#pragma unroll
    for (int b_ = 0; b_ < Bc; b_++) red[t][b_] = a[b_];
    __syncthreads();
    for (int s = 32; s > 0; s >>= 1) {
        if (t < s) {
#pragma unroll
            for (int b_ = 0; b_ < Bc; b_++) red[t][b_] += red[t + s][b_];
        }
        __syncthreads();
    }
    if (t < Bc) {
        float bb = bias ? bias[j] : 0.f;
        float vals[Bc];
        double mean = 0.0;
#pragma unroll
        for (int b_ = 0; b_ < Bc; b_++) { vals[b_] = red[0][b_] + bb; mean += (double)vals[b_]; }
        mean *= (1.0 / Bc);
        double var = 0.0;
#pragma unroll
        for (int b_ = 0; b_ < Bc; b_++) { double d = (double)vals[b_] - mean; var += d * d; }
        var *= (1.0 / Bc);
        float m = (float)mean;
        float r = (float)rsqrt(var + EPSc);
        float y = __fadd_rn(__fmul_rn(__fmul_rn(__fsub_rn(vals[t], m), r), g[j]), bta[j]);
        out[t * Cout + j] = (y >= 0.f) ? y : SLOPEc * y;
    }
}

__global__ void fc3_kernel(const float* __restrict__ in, const float* __restrict__ W,
                           const float* __restrict__ bias, float* __restrict__ out)
{
    int t = threadIdx.x;
    if (t >= Bc * 40) return;
    int b = t / 40, j = t % 40;
    float s = 0.f;
    for (int e = 0; e < 256; e++) s = fmaf(W[j * 256 + e], in[b * 256 + e], s);
    out[t] = __fadd_rn(s, bias[j]);
}

// ---------------- host orchestration ----------------

static void run_edge_block(const float* xin, int C, int O,
                           const float* wTseg, const float* g, const float* bta,
                           float* xout,
                           float2* dist, float2* xxp, int* idxp,
                           float* ymax, double* statseg)
{
    xx_kernel<<<(Bc * Nc + 255) / 256, 256>>>(xin, xxp, C);
    dist_kernel<<<dim3(Nc / 64, Nc / 64, Bc), 256>>>(xin, xxp, dist, C);
    topk_kernel<<<Bc * Nc, 256>>>(dist, idxp);
    size_t shm = (size_t)(2 * (2 * C * Kc + C)) * sizeof(float) + 2 * Kc * sizeof(int);
    edgeconv_kernel<<<dim3(Nc / 2, Bc), O, shm>>>(xin, wTseg, idxp, ymax, statseg, C, O);
    bnapply_kernel<<<dim3(Nc / 32, O / 32, Bc), dim3(32, 8)>>>(ymax, statseg, g, bta, xout, O,
                                                               1.0 / (double)(Bc * Nc * Kc));
}

extern "C" void kernel_launch(void* const* d_in, const int* in_sizes, int n_in,
                              void* d_out, int out_size)
{
    const float* x   = (const float*)d_in[0];
    const float* w1  = (const float*)d_in[1];
    const float* w2  = (const float*)d_in[2];
    const float* w3  = (const float*)d_in[3];
    const float* w4  = (const float*)d_in[4];
    const float* w5  = (const float*)d_in[5];
    const float* lw1 = (const float*)d_in[6];
    const float* lw2 = (const float*)d_in[7];
    const float* lb2 = (const float*)d_in[8];
    const float* lw3 = (const float*)d_in[9];
    const float* lb3 = (const float*)d_in[10];
    const float* g1 = (const float*)d_in[11]; const float* b1 = (const float*)d_in[12];
    const float* g2 = (const float*)d_in[13]; const float* b2 = (const float*)d_in[14];
    const float* g3 = (const float*)d_in[15]; const float* b3 = (const float*)d_in[16];
    const float* g4 = (const float*)d_in[17]; const float* b4 = (const float*)d_in[18];
    const float* g5 = (const float*)d_in[19]; const float* b5 = (const float*)d_in[20];
    const float* g6 = (const float*)d_in[21]; const float* b6 = (const float*)d_in[22];
    const float* g7 = (const float*)d_in[23]; const float* b7 = (const float*)d_in[24];

    float *wT, *ymax, *x1b, *x2b, *x3b, *x4b, *z5, *pbuf, *h1, *h2;
    float2 *dist, *xxp;
    double* stats;
    int* idxp;
    cudaGetSymbolAddress((void**)&dist,  g_dist2);
    cudaGetSymbolAddress((void**)&xxp,   g_xx2);
    cudaGetSymbolAddress((void**)&idxp,  g_idx);
    cudaGetSymbolAddress((void**)&wT,    g_wT);
    cudaGetSymbolAddress((void**)&ymax,  g_ymax);
    cudaGetSymbolAddress((void**)&stats, g_statsd);
    cudaGetSymbolAddress((void**)&x1b,   g_x1);
    cudaGetSymbolAddress((void**)&x2b,   g_x2);
    cudaGetSymbolAddress((void**)&x3b,   g_x3);
    cudaGetSymbolAddress((void**)&x4b,   g_x4);
    cudaGetSymbolAddress((void**)&z5,    g_z5);
    cudaGetSymbolAddress((void**)&pbuf,  g_p);
    cudaGetSymbolAddress((void**)&h1,    g_h1);
    cudaGetSymbolAddress((void**)&h2,    g_h2);

    transpose_all<<<(90496 + 255) / 256, 256>>>(w1, w2, w3, w4, wT);
    zerostats_kernel<<<12, 256>>>(stats);

    run_edge_block(x,   3,   64,  wT + WT_OFF1, g1, b1, x1b, dist, xxp, idxp, ymax, stats + ST_OFF1);
    run_edge_block(x1b, 64,  64,  wT + WT_OFF2, g2, b2, x2b, dist, xxp, idxp, ymax, stats + ST_OFF2);
    run_edge_block(x2b, 64,  128, wT + WT_OFF3, g3, b3, x3b, dist, xxp, idxp, ymax, stats + ST_OFF3);
    run_edge_block(x3b, 128, 256, wT + WT_OFF4, g4, b4, x4b, dist, xxp, idxp, ymax, stats + ST_OFF4);

    conv5_kernel<<<dim3(Nc / 64, EMBc / 64, Bc), 256>>>(w5, x1b, x2b, x3b, x4b, z5, stats + ST_OFF5);
    pool5_kernel<<<dim3(EMBc, Bc), 32>>>(z5, stats + ST_OFF5, g5, b5, pbuf);

    fc_bn_kernel<<<512, 64>>>(pbuf, lw1, nullptr, g6, b6, h1, 2 * EMBc, 512);
    fc_bn_kernel<<<256, 64>>>(h1, lw2, lb2, g7, b7, h2, 512, 256);
    fc3_kernel<<<1, 320>>>(h2, lw3, lb3, (float*)d_out);
}

// round 14
// speedup vs baseline: 1.3626x; 1.0878x over previous
#include <cuda_runtime.h>
#include <cstdint>
#include <math.h>

#define Bc 8
#define Nc 2048
#define Kc 20
#define EMBc 1024
#define EPSc 1e-5
#define SLOPEc 0.2f

typedef unsigned long long u64;

// ---------------- packed f32x2 helpers (exact dual IEEE fp32 ops) ----------------
__device__ __forceinline__ u64 pack2(float lo, float hi)
{
    u64 r; asm("mov.b64 %0, {%1, %2};" : "=l"(r) : "f"(lo), "f"(hi)); return r;
}
__device__ __forceinline__ void unpack2(u64 v, float& lo, float& hi)
{
    asm("mov.b64 {%0, %1}, %2;" : "=f"(lo), "=f"(hi) : "l"(v));
}
__device__ __forceinline__ u64 fma2(u64 a, u64 b, u64 c)
{
    u64 d; asm("fma.rn.f32x2 %0, %1, %2, %3;" : "=l"(d) : "l"(a), "l"(b), "l"(c)); return d;
}
__device__ __forceinline__ u64 add2(u64 a, u64 b)
{
    u64 d; asm("add.rn.f32x2 %0, %1, %2;" : "=l"(d) : "l"(a), "l"(b)); return d;
}
__device__ __forceinline__ u64 sub2(u64 a, u64 b)
{
    return fma2(b, 0xBF800000BF800000ull, a);
}

// ---------------- scratch ----------------
__device__ float2 g_dist2[(size_t)Bc * Nc * Nc];
__device__ float2 g_xx2[Bc * Nc];
__device__ int    g_idx[Bc * Nc * Kc];
__device__ float  g_x1[Bc * 64 * Nc];
__device__ float  g_x2[Bc * 64 * Nc];
__device__ float  g_x3[Bc * 128 * Nc];
__device__ float  g_x4[Bc * 256 * Nc];
__device__ float  g_wT[90496];
__device__ float  g_ymax[Bc * Nc * 256];
__device__ double g_statsd[3072];
__device__ float  g_z5[Bc * EMBc * Nc];
__device__ float  g_p[Bc * 2 * EMBc];
__device__ float  g_h1[Bc * 512];
__device__ float  g_h2[Bc * 256];

#define WT_OFF1 0
#define WT_OFF2 384
#define WT_OFF3 8576
#define WT_OFF4 24960
#define ST_OFF1 0
#define ST_OFF2 128
#define ST_OFF3 256
#define ST_OFF4 512
#define ST_OFF5 1024

#define NPAIRS 528   // 32*33/2 lower-triangle 64x64 tile pairs

// ---------------- double-float helpers ----------------
__device__ __forceinline__ void two_sum(float a, float b, float& s, float& e)
{
    s = __fadd_rn(a, b);
    float bp = __fsub_rn(s, a);
    e = __fadd_rn(__fsub_rn(a, __fsub_rn(s, bp)), __fsub_rn(b, bp));
}

__device__ __forceinline__ float2 dd_sub(float ah, float al, float2 b)
{
    float s1  = __fsub_rn(ah, b.x);
    float v   = __fsub_rn(s1, ah);
    float err = __fsub_rn(__fsub_rn(ah, __fsub_rn(s1, v)), __fadd_rn(b.x, v));
    err = __fadd_rn(err, __fsub_rn(al, b.y));
    float hi = __fadd_rn(s1, err);
    float lo = __fsub_rn(err, __fsub_rn(hi, s1));
    return make_float2(hi, lo);
}

// ---------------- kernels ----------------

// w1:(64,6) w2:(64,128) w3:(128,128) w4:(256,256)
__global__ void transpose_all(const float* __restrict__ w1, const float* __restrict__ w2,
                              const float* __restrict__ w3, const float* __restrict__ w4,
                              float* __restrict__ wT)
{
    int t = blockIdx.x * blockDim.x + threadIdx.x;
    const float* w; int O, C2, base, li;
    if (t < 384)        { w = w1; O = 64;  C2 = 6;   base = WT_OFF1; li = t; }
    else if (t < 8576)  { w = w2; O = 64;  C2 = 128; base = WT_OFF2; li = t - 384; }
    else if (t < 24960) { w = w3; O = 128; C2 = 128; base = WT_OFF3; li = t - 8576; }
    else if (t < 90496) { w = w4; O = 256; C2 = 256; base = WT_OFF4; li = t - 24960; }
    else return;
    int o = li / C2, c = li % C2;
    wT[base + c * O + o] = w[li];
}

__global__ void zerostats_kernel(double* __restrict__ stats)
{
    int t = blockIdx.x * blockDim.x + threadIdx.x;
    if (t < 3072) stats[t] = 0.0;
}

__global__ void xx_kernel(const float* __restrict__ x, float2* __restrict__ xx2, int C)
{
    int i = blockIdx.x * blockDim.x + threadIdx.x;
    if (i >= Bc * Nc) return;
    int b = i / Nc, n = i % Nc;
    double s = 0.0;
    for (int c = 0; c < C; c++) {
        double v = (double)x[((size_t)b * C + c) * Nc + n];
        s += v * v;
    }
    float hi = (float)s;
    float lo = (float)(s - (double)hi);
    xx2[i] = make_float2(hi, lo);
}

// symmetric dist: lower-triangle 64x64 tile pairs; each tile computed once (dd chain
// bit-identical to R13), written to pd[n][m] (sub xn then xm) and, off-diagonal,
// to pd[m][n] (sub xm then xn — exactly the chain R13 used for those rows).
// Stores vectorized as float4 pairs.
__global__ void dist_sym_kernel(const float* __restrict__ x, const float2* __restrict__ xx2,
                                float2* __restrict__ dist, int C)
{
    __shared__ float sn[8][64];
    __shared__ float sm_[8][64];
    int b = blockIdx.z;
    int p = blockIdx.x;
    float ff = sqrtf(8.f * (float)p + 1.f);
    int bi = (int)((ff - 1.f) * 0.5f);
    while ((bi + 1) * (bi + 2) / 2 <= p) bi++;
    while (bi * (bi + 1) / 2 > p) bi--;
    int bj = p - bi * (bi + 1) / 2;
    int n0 = bi * 64, m0 = bj * 64;

    int t = threadIdx.x;
    int tx = t & 15, ty = t >> 4;
    u64 s2[4][2], e2[4][2];
#pragma unroll
    for (int i = 0; i < 4; i++)
#pragma unroll
        for (int jp = 0; jp < 2; jp++) { s2[i][jp] = 0ull; e2[i][jp] = 0ull; }
    const float* xb = x + (size_t)b * C * Nc;

    for (int c0 = 0; c0 < C; c0 += 8) {
#pragma unroll
        for (int r = 0; r < 2; r++) {
            int ei = t + r * 256;
            int cc = ei >> 6, j = ei & 63;
            int c = c0 + cc;
            sn[cc][j]  = (c < C) ? xb[(size_t)c * Nc + n0 + j] : 0.f;
            sm_[cc][j] = (c < C) ? xb[(size_t)c * Nc + m0 + j] : 0.f;
        }
        __syncthreads();
        u64 f2[4][2];
#pragma unroll
        for (int i = 0; i < 4; i++) { f2[i][0] = 0ull; f2[i][1] = 0ull; }
#pragma unroll
        for (int q = 0; q < 8; q++) {
            float4 nv = *(const float4*)&sn[q][ty * 4];
            float4 mv = *(const float4*)&sm_[q][tx * 4];
            u64 m01 = pack2(mv.x, mv.y);
            u64 m23 = pack2(mv.z, mv.w);
            float nn[4] = {nv.x, nv.y, nv.z, nv.w};
#pragma unroll
            for (int i = 0; i < 4; i++) {
                u64 np = pack2(nn[i], nn[i]);
                f2[i][0] = fma2(np, m01, f2[i][0]);
                f2[i][1] = fma2(np, m23, f2[i][1]);
            }
        }
#pragma unroll
        for (int i = 0; i < 4; i++)
#pragma unroll
            for (int jp = 0; jp < 2; jp++) {
                u64 tt = add2(s2[i][jp], f2[i][jp]);
                u64 bp = sub2(tt, s2[i][jp]);
                u64 ea = sub2(s2[i][jp], sub2(tt, bp));
                u64 eb = sub2(f2[i][jp], bp);
                e2[i][jp] = add2(e2[i][jp], add2(ea, eb));
                s2[i][jp] = tt;
            }
        __syncthreads();
    }

    // unpack dd dot*2 into dh/dl
    float dh[4][4], dl[4][4];
#pragma unroll
    for (int i = 0; i < 4; i++) {
        float sa[4], ea[4];
        unpack2(s2[i][0], sa[0], sa[1]);
        unpack2(s2[i][1], sa[2], sa[3]);
        unpack2(e2[i][0], ea[0], ea[1]);
        unpack2(e2[i][1], ea[2], ea[3]);
#pragma unroll
        for (int j = 0; j < 4; j++) {
            float h, l;
            two_sum(sa[j], ea[j], h, l);
            dh[i][j] = __fmul_rn(h, 2.f);
            dl[i][j] = __fmul_rn(l, 2.f);
        }
    }

    int n = n0 + ty * 4, m = m0 + tx * 4;
    float2 xn[4], xm[4];
#pragma unroll
    for (int i = 0; i < 4; i++) { xn[i] = xx2[b * Nc + n + i]; xm[i] = xx2[b * Nc + m + i]; }
    float2* dr = dist + (size_t)b * Nc * Nc;

    // normal orientation: row n, subtract xn then xm
#pragma unroll
    for (int i = 0; i < 4; i++) {
        float2 row[4];
#pragma unroll
        for (int j = 0; j < 4; j++) {
            float2 r1 = dd_sub(dh[i][j], dl[i][j], xn[i]);
            row[j] = dd_sub(r1.x, r1.y, xm[j]);
        }
        float4* dst = (float4*)(dr + (size_t)(n + i) * Nc + m);
        dst[0] = make_float4(row[0].x, row[0].y, row[1].x, row[1].y);
        dst[1] = make_float4(row[2].x, row[2].y, row[3].x, row[3].y);
    }

    // mirrored orientation: row m, subtract xm then xn (off-diagonal pairs only)
    if (bi != bj) {
#pragma unroll
        for (int j = 0; j < 4; j++) {
            float2 col[4];
#pragma unroll
            for (int i = 0; i < 4; i++) {
                float2 r1 = dd_sub(dh[i][j], dl[i][j], xm[j]);
                col[i] = dd_sub(r1.x, r1.y, xn[i]);
            }
            float4* dst = (float4*)(dr + (size_t)(m + j) * Nc + n);
            dst[0] = make_float4(col[0].x, col[0].y, col[1].x, col[1].y);
            dst[1] = make_float4(col[2].x, col[2].y, col[3].x, col[3].y);
        }
    }
}

// merge-based top-20 (R11-proven): per-thread Batcher sort of 8 keys, shuffle-only
// warp merge, warp-0 merges the 8 per-warp lists. Order: (val desc, idx asc).
#define CE(i, j) { \
    bool sw = (vx[j] > vx[i]) || (vx[j] == vx[i] && (vy[j] > vy[i] || (vy[j] == vy[i] && vi[j] < vi[i]))); \
    if (sw) { float tx_ = vx[i]; vx[i] = vx[j]; vx[j] = tx_; \
              float ty_ = vy[i]; vy[i] = vy[j]; vy[j] = ty_; \
              int   ti_ = vi[i]; vi[i] = vi[j]; vi[j] = ti_; } }

__global__ void topk_kernel(const float2* __restrict__ dist, int* __restrict__ idx)
{
    int row = blockIdx.x;
    int t = threadIdx.x;
    int lane = t & 31, wid = t >> 5;
    const float4* d4 = (const float4*)(dist + (size_t)row * Nc) + t * 4;
    float vx[8], vy[8];
    int vi[8];
#pragma unroll
    for (int q = 0; q < 4; q++) {
        float4 f = d4[q];
        vx[2 * q]     = f.x; vy[2 * q]     = f.y;
        vx[2 * q + 1] = f.z; vy[2 * q + 1] = f.w;
        vi[2 * q]     = t * 8 + 2 * q;
        vi[2 * q + 1] = t * 8 + 2 * q + 1;
    }
    CE(0,1) CE(2,3) CE(4,5) CE(6,7)
    CE(0,2) CE(1,3) CE(4,6) CE(5,7)
    CE(1,2) CE(5,6)
    CE(0,4) CE(1,5) CE(2,6) CE(3,7)
    CE(2,4) CE(3,5)
    CE(1,2) CE(3,4) CE(5,6)

    __shared__ float swx[8][Kc], swy[8][Kc];
    __shared__ int   swi[8][Kc];

    for (int kk = 0; kk < Kc; kk++) {
        float bx = vx[0], by = vy[0];
        int bi = vi[0], bl = lane;
#pragma unroll
        for (int off = 16; off; off >>= 1) {
            float ox = __shfl_xor_sync(0xffffffffu, bx, off);
            float oy = __shfl_xor_sync(0xffffffffu, by, off);
            int   oi = __shfl_xor_sync(0xffffffffu, bi, off);
            int   ol = __shfl_xor_sync(0xffffffffu, bl, off);
            if (ox > bx || (ox == bx && (oy > by || (oy == by && oi < bi)))) {
                bx = ox; by = oy; bi = oi; bl = ol;
            }
        }
        if (lane == 0) { swx[wid][kk] = bx; swy[wid][kk] = by; swi[wid][kk] = bi; }
        if (lane == bl) {
#pragma unroll
            for (int q = 0; q < 7; q++) { vx[q] = vx[q + 1]; vy[q] = vy[q + 1]; vi[q] = vi[q + 1]; }
            vx[7] = -INFINITY; vy[7] = -INFINITY; vi[7] = 0x7FFFFFFF;
        }
    }
    __syncthreads();

    if (t < 32) {
        bool act = lane < 8;
        int pos = 0;
        float hx = act ? swx[lane][0] : -INFINITY;
        float hy = act ? swy[lane][0] : -INFINITY;
        int   hidx = act ? swi[lane][0] : 0x7FFFFFFF;
        int* out = idx + (size_t)row * Kc;
        for (int kk = 0; kk < Kc; kk++) {
            float bx = hx, by = hy;
            int bi = hidx, bl = lane;
#pragma unroll
            for (int off = 16; off; off >>= 1) {
                float ox = __shfl_xor_sync(0xffffffffu, bx, off);
                float oy = __shfl_xor_sync(0xffffffffu, by, off);
                int   oi = __shfl_xor_sync(0xffffffffu, bi, off);
                int   ol = __shfl_xor_sync(0xffffffffu, bl, off);
                if (ox > bx || (ox == bx && (oy > by || (oy == by && oi < bi)))) {
                    bx = ox; by = oy; bi = oi; bl = ol;
                }
            }
            if (lane == 0) out[kk] = bi;
            if (lane == bl) {
                pos++;
                if (pos < Kc) { hx = swx[lane][pos]; hy = swy[lane][pos]; hidx = swi[lane][pos]; }
                else          { hx = -INFINITY; hy = -INFINITY; hidx = 0x7FFFFFFF; }
            }
        }
    }
}

// fused edgeconv: G=2 n per block, LDS.128 feat loads, FFMA2 mainloop (bit-identical
// per-n chains), dd fp32 stat accumulation -> single fp64 atomic per channel pair.
__global__ void edgeconv_kernel(const float* __restrict__ xin, const float* __restrict__ wT,
                                const int* __restrict__ idx, float* __restrict__ ymax,
                                double* __restrict__ stats, int C, int O)
{
    extern __shared__ float shm[];
    int nA = blockIdx.x * 2, nB = nA + 1;
    int b = blockIdx.y, t = threadIdx.x;
    int C2 = 2 * C;
    float* featA = shm;
    float* featB = shm + C2 * Kc;
    float* ctrA  = featB + C2 * Kc;
    float* ctrB  = ctrA + C;
    int*   sidx  = (int*)(ctrB + C);

    if (t < Kc)          sidx[t]     = idx[((size_t)b * Nc + nA) * Kc + t];
    else if (t < 2 * Kc) sidx[t]     = idx[((size_t)b * Nc + nB) * Kc + (t - Kc)];
    for (int c = t; c < C; c += blockDim.x) {
        ctrA[c] = xin[((size_t)b * C + c) * Nc + nA];
        ctrB[c] = xin[((size_t)b * C + c) * Nc + nB];
    }
    __syncthreads();
    for (int e = t; e < C * Kc; e += blockDim.x) {
        int c = e / Kc, k = e - c * Kc;
        float cvA = ctrA[c], cvB = ctrB[c];
        float nvA = xin[((size_t)b * C + c) * Nc + sidx[k]];
        float nvB = xin[((size_t)b * C + c) * Nc + sidx[Kc + k]];
        featA[c * Kc + k]       = __fsub_rn(nvA, cvA);
        featA[(C + c) * Kc + k] = cvA;
        featB[c * Kc + k]       = __fsub_rn(nvB, cvB);
        featB[(C + c) * Kc + k] = cvB;
    }
    __syncthreads();

    u64 accA[Kc / 2], accB[Kc / 2];
#pragma unroll
    for (int p = 0; p < Kc / 2; p++) { accA[p] = 0ull; accB[p] = 0ull; }

    const float* wptr = wT + t;
#pragma unroll 2
    for (int c2 = 0; c2 < C2; c2++) {
        float w = __ldg(wptr + c2 * O);
        u64 wp = pack2(w, w);
        const ulonglong2* fA = reinterpret_cast<const ulonglong2*>(featA + c2 * Kc);
        const ulonglong2* fB = reinterpret_cast<const ulonglong2*>(featB + c2 * Kc);
#pragma unroll
        for (int p = 0; p < 5; p++) {
            ulonglong2 fa = fA[p];
            accA[2 * p]     = fma2(fa.x, wp, accA[2 * p]);
            accA[2 * p + 1] = fma2(fa.y, wp, accA[2 * p + 1]);
        }
#pragma unroll
        for (int p = 0; p < 5; p++) {
            ulonglong2 fb = fB[p];
            accB[2 * p]     = fma2(fb.x, wp, accB[2 * p]);
            accB[2 * p + 1] = fma2(fb.y, wp, accB[2 * p + 1]);
        }
    }

    float acc[Kc];
    double Stot = 0.0, Qtot = 0.0;
#pragma unroll
    for (int half = 0; half < 2; half++) {
        u64* a2 = half ? accB : accA;
#pragma unroll
        for (int p = 0; p < Kc / 2; p++) unpack2(a2[p], acc[2 * p], acc[2 * p + 1]);
        float m = acc[0];
        float s = 0.f, se = 0.f, q = 0.f, qe = 0.f;
#pragma unroll
        for (int k = 0; k < Kc; k++) {
            float a = acc[k];
            m = fmaxf(m, a);
            float th, te;
            two_sum(s, a, th, te);
            s = th; se = __fadd_rn(se, te);
            float ph = __fmul_rn(a, a);
            float pl = fmaf(a, a, -ph);
            two_sum(q, ph, th, te);
            q = th; qe = __fadd_rn(qe, __fadd_rn(te, pl));
        }
        int n = half ? nB : nA;
        ymax[((size_t)b * Nc + n) * O + t] = m;
        Stot += (double)s + (double)se;
        Qtot += (double)q + (double)qe;
    }
    atomicAdd(&stats[t], Stot);
    atomicAdd(&stats[O + t], Qtot);
}

// BN + lrelu on max-pooled values, smem-tile transpose [b][n][o] -> [b][o][n]
__global__ void bnapply_kernel(const float* __restrict__ ymax, const double* __restrict__ stats,
                               const float* __restrict__ g, const float* __restrict__ bta,
                               float* __restrict__ xout, int O, double invcnt)
{
    __shared__ float tile[32][33];
    int b  = blockIdx.z;
    int o0 = blockIdx.y * 32;
    int n0 = blockIdx.x * 32;
    int tx = threadIdx.x, ty = threadIdx.y;
    int o = o0 + tx;
    double mean = stats[o] * invcnt;
    double var  = stats[O + o] * invcnt - mean * mean;
    float m = (float)mean;
    float r = (float)rsqrt(var + EPSc);
    float gg = g[o], bb = bta[o];
#pragma unroll
    for (int rr = 0; rr < 4; rr++) {
        int n = n0 + ty + rr * 8;
        float vv = ymax[((size_t)b * Nc + n) * O + o];
        float y = __fadd_rn(__fmul_rn(__fmul_rn(__fsub_rn(vv, m), r), gg), bb);
        tile[ty + rr * 8][tx] = (y >= 0.f) ? y : SLOPEc * y;
    }
    __syncthreads();
#pragma unroll
    for (int rr = 0; rr < 4; rr++) {
        int oo = o0 + ty + rr * 8;
        xout[((size_t)b * O + oo) * Nc + n0 + tx] = tile[tx][ty + rr * 8];
    }
}

// conv5 with FFMA2 mainloop; dd per-thread stats -> fp64 smem/global atomics
__global__ void conv5_kernel(const float* __restrict__ w5,
                             const float* __restrict__ x1, const float* __restrict__ x2,
                             const float* __restrict__ x3, const float* __restrict__ x4,
                             float* __restrict__ z, double* __restrict__ stats)
{
    __shared__ float As[16][68];
    __shared__ float Bs[16][64];
    __shared__ double rs[64], rss[64];
    int b  = blockIdx.z;
    int o0 = blockIdx.y * 64;
    int n0 = blockIdx.x * 64;
    int t = threadIdx.x;
    int tx = t & 15, ty = t >> 4;
    u64 acc2[4][2];
#pragma unroll
    for (int i = 0; i < 4; i++) { acc2[i][0] = 0ull; acc2[i][1] = 0ull; }

    for (int c0 = 0; c0 < 512; c0 += 16) {
#pragma unroll
        for (int r = 0; r < 4; r++) {
            int e = t + r * 256;
            int oo = e >> 4, cc = e & 15;
            As[cc][oo] = w5[(size_t)(o0 + oo) * 512 + c0 + cc];
            int cc2 = e >> 6, jj = e & 63;
            int ch = c0 + cc2;
            const float* src; int cl, Cb;
            if (ch < 64)       { src = x1; cl = ch;       Cb = 64;  }
            else if (ch < 128) { src = x2; cl = ch - 64;  Cb = 64;  }
            else if (ch < 256) { src = x3; cl = ch - 128; Cb = 128; }
            else               { src = x4; cl = ch - 256; Cb = 256; }
            Bs[cc2][jj] = src[((size_t)b * Cb + cl) * Nc + n0 + jj];
        }
        __syncthreads();
#pragma unroll
        for (int cc = 0; cc < 16; cc++) {
            float4 av4 = *(const float4*)&As[cc][ty * 4];
            float4 bv4 = *(const float4*)&Bs[cc][tx * 4];
            u64 b01 = pack2(bv4.x, bv4.y);
            u64 b23 = pack2(bv4.z, bv4.w);
            float av[4] = {av4.x, av4.y, av4.z, av4.w};
#pragma unroll
            for (int i = 0; i < 4; i++) {
                u64 ap = pack2(av[i], av[i]);
                acc2[i][0] = fma2(ap, b01, acc2[i][0]);
                acc2[i][1] = fma2(ap, b23, acc2[i][1]);
            }
        }
        __syncthreads();
    }
    float acc[4][4];
#pragma unroll
    for (int i = 0; i < 4; i++) {
        unpack2(acc2[i][0], acc[i][0], acc[i][1]);
        unpack2(acc2[i][1], acc[i][2], acc[i][3]);
    }
    if (t < 64) { rs[t] = 0.0; rss[t] = 0.0; }
    __syncthreads();
#pragma unroll
    for (int i = 0; i < 4; i++) {
        int o = o0 + ty * 4 + i;
        float s = 0.f, se = 0.f, q = 0.f, qe = 0.f;
#pragma unroll
        for (int j = 0; j < 4; j++) {
            float a = acc[i][j];
            float th, te;
            two_sum(s, a, th, te);
            s = th; se = __fadd_rn(se, te);
            float ph = __fmul_rn(a, a);
            float pl = fmaf(a, a, -ph);
            two_sum(q, ph, th, te);
            q = th; qe = __fadd_rn(qe, __fadd_rn(te, pl));
        }
        atomicAdd(&rs[ty * 4 + i],  (double)s + (double)se);
        atomicAdd(&rss[ty * 4 + i], (double)q + (double)qe);
        float4 v4 = make_float4(acc[i][0], acc[i][1], acc[i][2], acc[i][3]);
        *reinterpret_cast<float4*>(&z[((size_t)b * EMBc + o) * Nc + n0 + tx * 4]) = v4;
    }
    __syncthreads();
    if (t < 64) {
        atomicAdd(&stats[o0 + t], rs[t]);
        atomicAdd(&stats[EMBc + o0 + t], rss[t]);
    }
}

__global__ void pool5_kernel(const float* __restrict__ z, const double* __restrict__ stats,
                             const float* __restrict__ g, const float* __restrict__ bta,
                             float* __restrict__ p)
{
    int o = blockIdx.x, b = blockIdx.y, lane = threadIdx.x;
    const double inv = 1.0 / (double)(Bc * Nc);
    double mean = stats[o] * inv;
    double var  = stats[EMBc + o] * inv - mean * mean;
    float m = (float)mean;
    float r = (float)rsqrt(var + EPSc);
    float gg = g[o], bb = bta[o];
    const float* row = z + ((size_t)b * EMBc + o) * Nc;
    float mx = -INFINITY, sm = 0.f;
    for (int j = lane; j < Nc; j += 32) {
        float v = __fadd_rn(__fmul_rn(__fmul_rn(__fsub_rn(row[j], m), r), gg), bb);
        v = (v >= 0.f) ? v : SLOPEc * v;
        mx = fmaxf(mx, v);
        sm += v;
    }
    for (int off = 16; off; off >>= 1) {
        mx = fmaxf(mx, __shfl_xor_sync(0xffffffffu, mx, off));
        sm += __shfl_xor_sync(0xffffffffu, sm, off);
    }
    if (lane == 0) {
        p[b * 2 * EMBc + o] = mx;
        p[b * 2 * EMBc + EMBc + o] = sm * (1.0f / Nc);
    }
}

__global__ void fc_bn_kernel(const float* __restrict__ in, const float* __restrict__ W,
                             const float* __restrict__ bias, const float* __restrict__ g,
                             const float* __restrict__ bta, float* __restrict__ out,
                             int Cin, int Cout)
{
    int j = blockIdx.x, t = threadIdx.x;
    float a[Bc];
#pragma unroll
    for (int b_ = 0; b_ < Bc; b_++) a[b_] = 0.f;
    for (int e = t; e < Cin; e += 64) {
        float w = W[(size_t)j * Cin + e];
#pragma unroll
        for (int b_ = 0; b_ < Bc; b_++) a[b_] = fmaf(w, in[b_ * Cin + e], a[b_]);
    }
    __shared__ float red[64][Bc];
#pragma unroll
    for (int b_ = 0; b_ < Bc; b_++) red[t][b_] = a[b_];
    __syncthreads();
    for (int s = 32; s > 0; s >>= 1) {
        if (t < s) {
#pragma unroll
            for (int b_ = 0; b_ < Bc; b_++) red[t][b_] += red[t + s][b_];
        }
        __syncthreads();
    }
    if (t < Bc) {
        float bb = bias ? bias[j] : 0.f;
        float vals[Bc];
        double mean = 0.0;
#pragma unroll
        for (int b_ = 0; b_ < Bc; b_++) { vals[b_] = red[0][b_] + bb; mean += (double)vals[b_]; }
        mean *= (1.0 / Bc);
        double var = 0.0;
#pragma unroll
        for (int b_ = 0; b_ < Bc; b_++) { double d = (double)vals[b_] - mean; var += d * d; }
        var *= (1.0 / Bc);
        float m = (float)mean;
        float r = (float)rsqrt(var + EPSc);
        float y = __fadd_rn(__fmul_rn(__fmul_rn(__fsub_rn(vals[t], m), r), g[j]), bta[j]);
        out[t * Cout + j] = (y >= 0.f) ? y : SLOPEc * y;
    }
}

__global__ void fc3_kernel(const float* __restrict__ in, const float* __restrict__ W,
                           const float* __restrict__ bias, float* __restrict__ out)
{
    int t = threadIdx.x;
    if (t >= Bc * 40) return;
    int b = t / 40, j = t % 40;
    float s = 0.f;
    for (int e = 0; e < 256; e++) s = fmaf(W[j * 256 + e], in[b * 256 + e], s);
    out[t] = __fadd_rn(s, bias[j]);
}

// ---------------- host orchestration ----------------

static void run_edge_block(const float* xin, int C, int O,
                           const float* wTseg, const float* g, const float* bta,
                           float* xout,
                           float2* dist, float2* xxp, int* idxp,
                           float* ymax, double* statseg)
{
    xx_kernel<<<(Bc * Nc + 255) / 256, 256>>>(xin, xxp, C);
    dist_sym_kernel<<<dim3(NPAIRS, 1, Bc), 256>>>(xin, xxp, dist, C);
    topk_kernel<<<Bc * Nc, 256>>>(dist, idxp);
    size_t shm = (size_t)(2 * (2 * C * Kc + C)) * sizeof(float) + 2 * Kc * sizeof(int);
    edgeconv_kernel<<<dim3(Nc / 2, Bc), O, shm>>>(xin, wTseg, idxp, ymax, statseg, C, O);
    bnapply_kernel<<<dim3(Nc / 32, O / 32, Bc), dim3(32, 8)>>>(ymax, statseg, g, bta, xout, O,
                                                               1.0 / (double)(Bc * Nc * Kc));
}

extern "C" void kernel_launch(void* const* d_in, const int* in_sizes, int n_in,
                              void* d_out, int out_size)
{
    const float* x   = (const float*)d_in[0];
    const float* w1  = (const float*)d_in[1];
    const float* w2  = (const float*)d_in[2];
    const float* w3  = (const float*)d_in[3];
    const float* w4  = (const float*)d_in[4];
    const float* w5  = (const float*)d_in[5];
    const float* lw1 = (const float*)d_in[6];
    const float* lw2 = (const float*)d_in[7];
    const float* lb2 = (const float*)d_in[8];
    const float* lw3 = (const float*)d_in[9];
    const float* lb3 = (const float*)d_in[10];
    const float* g1 = (const float*)d_in[11]; const float* b1 = (const float*)d_in[12];
    const float* g2 = (const float*)d_in[13]; const float* b2 = (const float*)d_in[14];
    const float* g3 = (const float*)d_in[15]; const float* b3 = (const float*)d_in[16];
    const float* g4 = (const float*)d_in[17]; const float* b4 = (const float*)d_in[18];
    const float* g5 = (const float*)d_in[19]; const float* b5 = (const float*)d_in[20];
    const float* g6 = (const float*)d_in[21]; const float* b6 = (const float*)d_in[22];
    const float* g7 = (const float*)d_in[23]; const float* b7 = (const float*)d_in[24];

    float *wT, *ymax, *x1b, *x2b, *x3b, *x4b, *z5, *pbuf, *h1, *h2;
    float2 *dist, *xxp;
    double* stats;
    int* idxp;
    cudaGetSymbolAddress((void**)&dist,  g_dist2);
    cudaGetSymbolAddress((void**)&xxp,   g_xx2);
    cudaGetSymbolAddress((void**)&idxp,  g_idx);
    cudaGetSymbolAddress((void**)&wT,    g_wT);
    cudaGetSymbolAddress((void**)&ymax,  g_ymax);
    cudaGetSymbolAddress((void**)&stats, g_statsd);
    cudaGetSymbolAddress((void**)&x1b,   g_x1);
    cudaGetSymbolAddress((void**)&x2b,   g_x2);
    cudaGetSymbolAddress((void**)&x3b,   g_x3);
    cudaGetSymbolAddress((void**)&x4b,   g_x4);
    cudaGetSymbolAddress((void**)&z5,    g_z5);
    cudaGetSymbolAddress((void**)&pbuf,  g_p);
    cudaGetSymbolAddress((void**)&h1,    g_h1);
    cudaGetSymbolAddress((void**)&h2,    g_h2);

    transpose_all<<<(90496 + 255) / 256, 256>>>(w1, w2, w3, w4, wT);
    zerostats_kernel<<<12, 256>>>(stats);

    run_edge_block(x,   3,   64,  wT + WT_OFF1, g1, b1, x1b, dist, xxp, idxp, ymax, stats + ST_OFF1);
    run_edge_block(x1b, 64,  64,  wT + WT_OFF2, g2, b2, x2b, dist, xxp, idxp, ymax, stats + ST_OFF2);
    run_edge_block(x2b, 64,  128, wT + WT_OFF3, g3, b3, x3b, dist, xxp, idxp, ymax, stats + ST_OFF3);
    run_edge_block(x3b, 128, 256, wT + WT_OFF4, g4, b4, x4b, dist, xxp, idxp, ymax, stats + ST_OFF4);

    conv5_kernel<<<dim3(Nc / 64, EMBc / 64, Bc), 256>>>(w5, x1b, x2b, x3b, x4b, z5, stats + ST_OFF5);
    pool5_kernel<<<dim3(EMBc, Bc), 32>>>(z5, stats + ST_OFF5, g5, b5, pbuf);

    fc_bn_kernel<<<512, 64>>>(pbuf, lw1, nullptr, g6, b6, h1, 2 * EMBc, 512);
    fc_bn_kernel<<<256, 64>>>(h1, lw2, lb2, g7, b7, h2, 512, 256);
    fc3_kernel<<<1, 320>>>(h2, lw3, lb3, (float*)d_out);
}

// round 15
// speedup vs baseline: 1.4578x; 1.0699x over previous
#include <cuda_runtime.h>
#include <cstdint>
#include <math.h>

#define Bc 8
#define Nc 2048
#define Kc 20
#define EMBc 1024
#define EPSc 1e-5
#define SLOPEc 0.2f

typedef unsigned long long u64;

// ---------------- packed f32x2 helpers (exact dual IEEE fp32 ops) ----------------
__device__ __forceinline__ u64 pack2(float lo, float hi)
{
    u64 r; asm("mov.b64 %0, {%1, %2};" : "=l"(r) : "f"(lo), "f"(hi)); return r;
}
__device__ __forceinline__ void unpack2(u64 v, float& lo, float& hi)
{
    asm("mov.b64 {%0, %1}, %2;" : "=f"(lo), "=f"(hi) : "l"(v));
}
__device__ __forceinline__ u64 fma2(u64 a, u64 b, u64 c)
{
    u64 d; asm("fma.rn.f32x2 %0, %1, %2, %3;" : "=l"(d) : "l"(a), "l"(b), "l"(c)); return d;
}
__device__ __forceinline__ u64 add2(u64 a, u64 b)
{
    u64 d; asm("add.rn.f32x2 %0, %1, %2;" : "=l"(d) : "l"(a), "l"(b)); return d;
}
__device__ __forceinline__ u64 sub2(u64 a, u64 b)
{
    return fma2(b, 0xBF800000BF800000ull, a);
}

// monotone float -> sortable u32 (after -0 -> +0 canonicalization)
__device__ __forceinline__ unsigned sfloat(float f)
{
    unsigned b = __float_as_uint(__fadd_rn(f, 0.0f));   // -0 -> +0 (matches FSETP semantics)
    return b ^ ((unsigned)(((int)b) >> 31) | 0x80000000u);
}

// ---------------- scratch ----------------
__device__ float2 g_dist2[(size_t)Bc * Nc * Nc];
__device__ float2 g_xx2[Bc * Nc];
__device__ int    g_idx[Bc * Nc * Kc];
__device__ float  g_x1[Bc * 64 * Nc];
__device__ float  g_x2[Bc * 64 * Nc];
__device__ float  g_x3[Bc * 128 * Nc];
__device__ float  g_x4[Bc * 256 * Nc];
__device__ float  g_wT[90496];
__device__ float  g_ymax[Bc * Nc * 256];
__device__ double g_statsd[3072];
__device__ float  g_z5[Bc * EMBc * Nc];
__device__ float  g_p[Bc * 2 * EMBc];
__device__ float  g_h1[Bc * 512];
__device__ float  g_h2[Bc * 256];

#define WT_OFF1 0
#define WT_OFF2 384
#define WT_OFF3 8576
#define WT_OFF4 24960
#define ST_OFF1 0
#define ST_OFF2 128
#define ST_OFF3 256
#define ST_OFF4 512
#define ST_OFF5 1024

#define NPAIRS 528   // 32*33/2 lower-triangle 64x64 tile pairs

// ---------------- double-float helpers ----------------
__device__ __forceinline__ void two_sum(float a, float b, float& s, float& e)
{
    s = __fadd_rn(a, b);
    float bp = __fsub_rn(s, a);
    e = __fadd_rn(__fsub_rn(a, __fsub_rn(s, bp)), __fsub_rn(b, bp));
}

__device__ __forceinline__ float2 dd_sub(float ah, float al, float2 b)
{
    float s1  = __fsub_rn(ah, b.x);
    float v   = __fsub_rn(s1, ah);
    float err = __fsub_rn(__fsub_rn(ah, __fsub_rn(s1, v)), __fadd_rn(b.x, v));
    err = __fadd_rn(err, __fsub_rn(al, b.y));
    float hi = __fadd_rn(s1, err);
    float lo = __fsub_rn(err, __fsub_rn(hi, s1));
    return make_float2(hi, lo);
}

// ---------------- kernels ----------------

// w1:(64,6) w2:(64,128) w3:(128,128) w4:(256,256)
__global__ void transpose_all(const float* __restrict__ w1, const float* __restrict__ w2,
                              const float* __restrict__ w3, const float* __restrict__ w4,
                              float* __restrict__ wT)
{
    int t = blockIdx.x * blockDim.x + threadIdx.x;
    const float* w; int O, C2, base, li;
    if (t < 384)        { w = w1; O = 64;  C2 = 6;   base = WT_OFF1; li = t; }
    else if (t < 8576)  { w = w2; O = 64;  C2 = 128; base = WT_OFF2; li = t - 384; }
    else if (t < 24960) { w = w3; O = 128; C2 = 128; base = WT_OFF3; li = t - 8576; }
    else if (t < 90496) { w = w4; O = 256; C2 = 256; base = WT_OFF4; li = t - 24960; }
    else return;
    int o = li / C2, c = li % C2;
    wT[base + c * O + o] = w[li];
}

__global__ void zerostats_kernel(double* __restrict__ stats)
{
    int t = blockIdx.x * blockDim.x + threadIdx.x;
    if (t < 3072) stats[t] = 0.0;
}

__global__ void xx_kernel(const float* __restrict__ x, float2* __restrict__ xx2, int C)
{
    int i = blockIdx.x * blockDim.x + threadIdx.x;
    if (i >= Bc * Nc) return;
    int b = i / Nc, n = i % Nc;
    double s = 0.0;
    for (int c = 0; c < C; c++) {
        double v = (double)x[((size_t)b * C + c) * Nc + n];
        s += v * v;
    }
    float hi = (float)s;
    float lo = (float)(s - (double)hi);
    xx2[i] = make_float2(hi, lo);
}

// symmetric dist: lower-triangle 64x64 tile pairs, each computed once (bit-exact
// dd chains for both orientations). Stores vectorized as float4 pairs.
__global__ void dist_sym_kernel(const float* __restrict__ x, const float2* __restrict__ xx2,
                                float2* __restrict__ dist, int C)
{
    __shared__ float sn[8][64];
    __shared__ float sm_[8][64];
    int b = blockIdx.z;
    int p = blockIdx.x;
    float ff = sqrtf(8.f * (float)p + 1.f);
    int bi = (int)((ff - 1.f) * 0.5f);
    while ((bi + 1) * (bi + 2) / 2 <= p) bi++;
    while (bi * (bi + 1) / 2 > p) bi--;
    int bj = p - bi * (bi + 1) / 2;
    int n0 = bi * 64, m0 = bj * 64;

    int t = threadIdx.x;
    int tx = t & 15, ty = t >> 4;
    u64 s2[4][2], e2[4][2];
#pragma unroll
    for (int i = 0; i < 4; i++)
#pragma unroll
        for (int jp = 0; jp < 2; jp++) { s2[i][jp] = 0ull; e2[i][jp] = 0ull; }
    const float* xb = x + (size_t)b * C * Nc;

    for (int c0 = 0; c0 < C; c0 += 8) {
#pragma unroll
        for (int r = 0; r < 2; r++) {
            int ei = t + r * 256;
            int cc = ei >> 6, j = ei & 63;
            int c = c0 + cc;
            sn[cc][j]  = (c < C) ? xb[(size_t)c * Nc + n0 + j] : 0.f;
            sm_[cc][j] = (c < C) ? xb[(size_t)c * Nc + m0 + j] : 0.f;
        }
        __syncthreads();
        u64 f2[4][2];
#pragma unroll
        for (int i = 0; i < 4; i++) { f2[i][0] = 0ull; f2[i][1] = 0ull; }
#pragma unroll
        for (int q = 0; q < 8; q++) {
            float4 nv = *(const float4*)&sn[q][ty * 4];
            float4 mv = *(const float4*)&sm_[q][tx * 4];
            u64 m01 = pack2(mv.x, mv.y);
            u64 m23 = pack2(mv.z, mv.w);
            float nn[4] = {nv.x, nv.y, nv.z, nv.w};
#pragma unroll
            for (int i = 0; i < 4; i++) {
                u64 np = pack2(nn[i], nn[i]);
                f2[i][0] = fma2(np, m01, f2[i][0]);
                f2[i][1] = fma2(np, m23, f2[i][1]);
            }
        }
#pragma unroll
        for (int i = 0; i < 4; i++)
#pragma unroll
            for (int jp = 0; jp < 2; jp++) {
                u64 tt = add2(s2[i][jp], f2[i][jp]);
                u64 bp = sub2(tt, s2[i][jp]);
                u64 ea = sub2(s2[i][jp], sub2(tt, bp));
                u64 eb = sub2(f2[i][jp], bp);
                e2[i][jp] = add2(e2[i][jp], add2(ea, eb));
                s2[i][jp] = tt;
            }
        __syncthreads();
    }

    float dh[4][4], dl[4][4];
#pragma unroll
    for (int i = 0; i < 4; i++) {
        float sa[4], ea[4];
        unpack2(s2[i][0], sa[0], sa[1]);
        unpack2(s2[i][1], sa[2], sa[3]);
        unpack2(e2[i][0], ea[0], ea[1]);
        unpack2(e2[i][1], ea[2], ea[3]);
#pragma unroll
        for (int j = 0; j < 4; j++) {
            float h, l;
            two_sum(sa[j], ea[j], h, l);
            dh[i][j] = __fmul_rn(h, 2.f);
            dl[i][j] = __fmul_rn(l, 2.f);
        }
    }

    int n = n0 + ty * 4, m = m0 + tx * 4;
    float2 xn[4], xm[4];
#pragma unroll
    for (int i = 0; i < 4; i++) { xn[i] = xx2[b * Nc + n + i]; xm[i] = xx2[b * Nc + m + i]; }
    float2* dr = dist + (size_t)b * Nc * Nc;

#pragma unroll
    for (int i = 0; i < 4; i++) {
        float2 row[4];
#pragma unroll
        for (int j = 0; j < 4; j++) {
            float2 r1 = dd_sub(dh[i][j], dl[i][j], xn[i]);
            row[j] = dd_sub(r1.x, r1.y, xm[j]);
        }
        float4* dst = (float4*)(dr + (size_t)(n + i) * Nc + m);
        dst[0] = make_float4(row[0].x, row[0].y, row[1].x, row[1].y);
        dst[1] = make_float4(row[2].x, row[2].y, row[3].x, row[3].y);
    }

    if (bi != bj) {
#pragma unroll
        for (int j = 0; j < 4; j++) {
            float2 col[4];
#pragma unroll
            for (int i = 0; i < 4; i++) {
                float2 r1 = dd_sub(dh[i][j], dl[i][j], xm[j]);
                col[i] = dd_sub(r1.x, r1.y, xn[i]);
            }
            float4* dst = (float4*)(dr + (size_t)(m + j) * Nc + n);
            dst[0] = make_float4(col[0].x, col[0].y, col[1].x, col[1].y);
            dst[1] = make_float4(col[2].x, col[2].y, col[3].x, col[3].y);
        }
    }
}

// u64-key top-20: per-thread Batcher sort of 8 keys, 3-shfl pops (tie -> smaller
// lane == smaller idx), warp-0 merges per-warp lists (tie -> smaller warp == smaller idx)
#define CEK(i, j) { \
    bool sw = (key[j] > key[i]) || (key[j] == key[i] && vi[j] < vi[i]); \
    if (sw) { u64 tk_ = key[i]; key[i] = key[j]; key[j] = tk_; \
              int ti_ = vi[i]; vi[i] = vi[j]; vi[j] = ti_; } }

__global__ void topk_kernel(const float2* __restrict__ dist, int* __restrict__ idx)
{
    int row = blockIdx.x;
    int t = threadIdx.x;
    int lane = t & 31, wid = t >> 5;
    const float4* d4 = (const float4*)(dist + (size_t)row * Nc) + t * 4;
    u64 key[8];
    int vi[8];
#pragma unroll
    for (int q = 0; q < 4; q++) {
        float4 f = d4[q];
        key[2 * q]     = ((u64)sfloat(f.x) << 32) | sfloat(f.y);
        key[2 * q + 1] = ((u64)sfloat(f.z) << 32) | sfloat(f.w);
        vi[2 * q]     = t * 8 + 2 * q;
        vi[2 * q + 1] = t * 8 + 2 * q + 1;
    }
    // Batcher odd-even mergesort, 8 elements, (key desc, idx asc)
    CEK(0,1) CEK(2,3) CEK(4,5) CEK(6,7)
    CEK(0,2) CEK(1,3) CEK(4,6) CEK(5,7)
    CEK(1,2) CEK(5,6)
    CEK(0,4) CEK(1,5) CEK(2,6) CEK(3,7)
    CEK(2,4) CEK(3,5)
    CEK(1,2) CEK(3,4) CEK(5,6)

    __shared__ u64 swk[8][Kc];
    __shared__ int swi[8][Kc];

    for (int kk = 0; kk < Kc; kk++) {
        u64 bk = key[0];
        int bl = lane;
#pragma unroll
        for (int off = 16; off; off >>= 1) {
            u64 ok = __shfl_xor_sync(0xffffffffu, bk, off);
            int ol = __shfl_xor_sync(0xffffffffu, bl, off);
            if (ok > bk || (ok == bk && ol < bl)) { bk = ok; bl = ol; }
        }
        if (lane == 0) swk[wid][kk] = bk;
        if (lane == bl) {
            swi[wid][kk] = vi[0];
#pragma unroll
            for (int q = 0; q < 7; q++) { key[q] = key[q + 1]; vi[q] = vi[q + 1]; }
            key[7] = 0ull; vi[7] = 0x7FFFFFFF;
        }
    }
    __syncthreads();

    if (t < 32) {
        bool act = lane < 8;
        int pos = 0;
        u64 hk = act ? swk[lane][0] : 0ull;
        int hidx = act ? swi[lane][0] : 0x7FFFFFFF;
        int* out = idx + (size_t)row * Kc;
        for (int kk = 0; kk < Kc; kk++) {
            u64 bk = hk;
            int bl = lane;
#pragma unroll
            for (int off = 16; off; off >>= 1) {
                u64 ok = __shfl_xor_sync(0xffffffffu, bk, off);
                int ol = __shfl_xor_sync(0xffffffffu, bl, off);
                if (ok > bk || (ok == bk && ol < bl)) { bk = ok; bl = ol; }
            }
            int widx = __shfl_sync(0xffffffffu, hidx, bl);
            if (lane == 0) out[kk] = widx;
            if (lane == bl) {
                pos++;
                if (act && pos < Kc) { hk = swk[lane][pos]; hidx = swi[lane][pos]; }
                else                 { hk = 0ull; hidx = 0x7FFFFFFF; }
            }
        }
    }
}

// fused edgeconv: G=2 n per block, LDS.128 feat loads, FFMA2 mainloop (bit-identical
// per-n chains), dd fp32 stat accumulation -> single fp64 atomic per channel pair.
__global__ void edgeconv_kernel(const float* __restrict__ xin, const float* __restrict__ wT,
                                const int* __restrict__ idx, float* __restrict__ ymax,
                                double* __restrict__ stats, int C, int O)
{
    extern __shared__ float shm[];
    int nA = blockIdx.x * 2, nB = nA + 1;
    int b = blockIdx.y, t = threadIdx.x;
    int C2 = 2 * C;
    float* featA = shm;
    float* featB = shm + C2 * Kc;
    float* ctrA  = featB + C2 * Kc;
    float* ctrB  = ctrA + C;
    int*   sidx  = (int*)(ctrB + C);

    if (t < Kc)          sidx[t]     = idx[((size_t)b * Nc + nA) * Kc + t];
    else if (t < 2 * Kc) sidx[t]     = idx[((size_t)b * Nc + nB) * Kc + (t - Kc)];
    for (int c = t; c < C; c += blockDim.x) {
        ctrA[c] = xin[((size_t)b * C + c) * Nc + nA];
        ctrB[c] = xin[((size_t)b * C + c) * Nc + nB];
    }
    __syncthreads();
    for (int e = t; e < C * Kc; e += blockDim.x) {
        int c = e / Kc, k = e - c * Kc;
        float cvA = ctrA[c], cvB = ctrB[c];
        float nvA = xin[((size_t)b * C + c) * Nc + sidx[k]];
        float nvB = xin[((size_t)b * C + c) * Nc + sidx[Kc + k]];
        featA[c * Kc + k]       = __fsub_rn(nvA, cvA);
        featA[(C + c) * Kc + k] = cvA;
        featB[c * Kc + k]       = __fsub_rn(nvB, cvB);
        featB[(C + c) * Kc + k] = cvB;
    }
    __syncthreads();

    u64 accA[Kc / 2], accB[Kc / 2];
#pragma unroll
    for (int p = 0; p < Kc / 2; p++) { accA[p] = 0ull; accB[p] = 0ull; }

    const float* wptr = wT + t;
#pragma unroll 2
    for (int c2 = 0; c2 < C2; c2++) {
        float w = __ldg(wptr + c2 * O);
        u64 wp = pack2(w, w);
        const ulonglong2* fA = reinterpret_cast<const ulonglong2*>(featA + c2 * Kc);
        const ulonglong2* fB = reinterpret_cast<const ulonglong2*>(featB + c2 * Kc);
#pragma unroll
        for (int p = 0; p < 5; p++) {
            ulonglong2 fa = fA[p];
            accA[2 * p]     = fma2(fa.x, wp, accA[2 * p]);
            accA[2 * p + 1] = fma2(fa.y, wp, accA[2 * p + 1]);
        }
#pragma unroll
        for (int p = 0; p < 5; p++) {
            ulonglong2 fb = fB[p];
            accB[2 * p]     = fma2(fb.x, wp, accB[2 * p]);
            accB[2 * p + 1] = fma2(fb.y, wp, accB[2 * p + 1]);
        }
    }

    float acc[Kc];
    double Stot = 0.0, Qtot = 0.0;
#pragma unroll
    for (int half = 0; half < 2; half++) {
        u64* a2 = half ? accB : accA;
#pragma unroll
        for (int p = 0; p < Kc / 2; p++) unpack2(a2[p], acc[2 * p], acc[2 * p + 1]);
        float m = acc[0];
        float s = 0.f, se = 0.f, q = 0.f, qe = 0.f;
#pragma unroll
        for (int k = 0; k < Kc; k++) {
            float a = acc[k];
            m = fmaxf(m, a);
            float th, te;
            two_sum(s, a, th, te);
            s = th; se = __fadd_rn(se, te);
            float ph = __fmul_rn(a, a);
            float pl = fmaf(a, a, -ph);
            two_sum(q, ph, th, te);
            q = th; qe = __fadd_rn(qe, __fadd_rn(te, pl));
        }
        int n = half ? nB : nA;
        ymax[((size_t)b * Nc + n) * O + t] = m;
        Stot += (double)s + (double)se;
        Qtot += (double)q + (double)qe;
    }
    atomicAdd(&stats[t], Stot);
    atomicAdd(&stats[O + t], Qtot);
}

// BN + lrelu on max-pooled values, smem-tile transpose [b][n][o] -> [b][o][n]
__global__ void bnapply_kernel(const float* __restrict__ ymax, const double* __restrict__ stats,
                               const float* __restrict__ g, const float* __restrict__ bta,
                               float* __restrict__ xout, int O, double invcnt)
{
    __shared__ float tile[32][33];
    int b  = blockIdx.z;
    int o0 = blockIdx.y * 32;
    int n0 = blockIdx.x * 32;
    int tx = threadIdx.x, ty = threadIdx.y;
    int o = o0 + tx;
    double mean = stats[o] * invcnt;
    double var  = stats[O + o] * invcnt - mean * mean;
    float m = (float)mean;
    float r = (float)rsqrt(var + EPSc);
    float gg = g[o], bb = bta[o];
#pragma unroll
    for (int rr = 0; rr < 4; rr++) {
        int n = n0 + ty + rr * 8;
        float vv = ymax[((size_t)b * Nc + n) * O + o];
        float y = __fadd_rn(__fmul_rn(__fmul_rn(__fsub_rn(vv, m), r), gg), bb);
        tile[ty + rr * 8][tx] = (y >= 0.f) ? y : SLOPEc * y;
    }
    __syncthreads();
#pragma unroll
    for (int rr = 0; rr < 4; rr++) {
        int oo = o0 + ty + rr * 8;
        xout[((size_t)b * O + oo) * Nc + n0 + tx] = tile[tx][ty + rr * 8];
    }
}

// conv5 with FFMA2 mainloop; dd per-thread stats -> fp64 smem/global atomics
__global__ void conv5_kernel(const float* __restrict__ w5,
                             const float* __restrict__ x1, const float* __restrict__ x2,
                             const float* __restrict__ x3, const float* __restrict__ x4,
                             float* __restrict__ z, double* __restrict__ stats)
{
    __shared__ float As[16][68];
    __shared__ float Bs[16][64];
    __shared__ double rs[64], rss[64];
    int b  = blockIdx.z;
    int o0 = blockIdx.y * 64;
    int n0 = blockIdx.x * 64;
    int t = threadIdx.x;
    int tx = t & 15, ty = t >> 4;
    u64 acc2[4][2];
#pragma unroll
    for (int i = 0; i < 4; i++) { acc2[i][0] = 0ull; acc2[i][1] = 0ull; }

    for (int c0 = 0; c0 < 512; c0 += 16) {
#pragma unroll
        for (int r = 0; r < 4; r++) {
            int e = t + r * 256;
            int oo = e >> 4, cc = e & 15;
            As[cc][oo] = w5[(size_t)(o0 + oo) * 512 + c0 + cc];
            int cc2 = e >> 6, jj = e & 63;
            int ch = c0 + cc2;
            const float* src; int cl, Cb;
            if (ch < 64)       { src = x1; cl = ch;       Cb = 64;  }
            else if (ch < 128) { src = x2; cl = ch - 64;  Cb = 64;  }
            else if (ch < 256) { src = x3; cl = ch - 128; Cb = 128; }
            else               { src = x4; cl = ch - 256; Cb = 256; }
            Bs[cc2][jj] = src[((size_t)b * Cb + cl) * Nc + n0 + jj];
        }
        __syncthreads();
#pragma unroll
        for (int cc = 0; cc < 16; cc++) {
            float4 av4 = *(const float4*)&As[cc][ty * 4];
            float4 bv4 = *(const float4*)&Bs[cc][tx * 4];
            u64 b01 = pack2(bv4.x, bv4.y);
            u64 b23 = pack2(bv4.z, bv4.w);
            float av[4] = {av4.x, av4.y, av4.z, av4.w};
#pragma unroll
            for (int i = 0; i < 4; i++) {
                u64 ap = pack2(av[i], av[i]);
                acc2[i][0] = fma2(ap, b01, acc2[i][0]);
                acc2[i][1] = fma2(ap, b23, acc2[i][1]);
            }
        }
        __syncthreads();
    }
    float acc[4][4];
#pragma unroll
    for (int i = 0; i < 4; i++) {
        unpack2(acc2[i][0], acc[i][0], acc[i][1]);
        unpack2(acc2[i][1], acc[i][2], acc[i][3]);
    }
    if (t < 64) { rs[t] = 0.0; rss[t] = 0.0; }
    __syncthreads();
#pragma unroll
    for (int i = 0; i < 4; i++) {
        int o = o0 + ty * 4 + i;
        float s = 0.f, se = 0.f, q = 0.f, qe = 0.f;
#pragma unroll
        for (int j = 0; j < 4; j++) {
            float a = acc[i][j];
            float th, te;
            two_sum(s, a, th, te);
            s = th; se = __fadd_rn(se, te);
            float ph = __fmul_rn(a, a);
            float pl = fmaf(a, a, -ph);
            two_sum(q, ph, th, te);
            q = th; qe = __fadd_rn(qe, __fadd_rn(te, pl));
        }
        atomicAdd(&rs[ty * 4 + i],  (double)s + (double)se);
        atomicAdd(&rss[ty * 4 + i], (double)q + (double)qe);
        float4 v4 = make_float4(acc[i][0], acc[i][1], acc[i][2], acc[i][3]);
        *reinterpret_cast<float4*>(&z[((size_t)b * EMBc + o) * Nc + n0 + tx * 4]) = v4;
    }
    __syncthreads();
    if (t < 64) {
        atomicAdd(&stats[o0 + t], rs[t]);
        atomicAdd(&stats[EMBc + o0 + t], rss[t]);
    }
}

__global__ void pool5_kernel(const float* __restrict__ z, const double* __restrict__ stats,
                             const float* __restrict__ g, const float* __restrict__ bta,
                             float* __restrict__ p)
{
    int o = blockIdx.x, b = blockIdx.y, lane = threadIdx.x;
    const double inv = 1.0 / (double)(Bc * Nc);
    double mean = stats[o] * inv;
    double var  = stats[EMBc + o] * inv - mean * mean;
    float m = (float)mean;
    float r = (float)rsqrt(var + EPSc);
    float gg = g[o], bb = bta[o];
    const float* row = z + ((size_t)b * EMBc + o) * Nc;
    float mx = -INFINITY, sm = 0.f;
    for (int j = lane; j < Nc; j += 32) {
        float v = __fadd_rn(__fmul_rn(__fmul_rn(__fsub_rn(row[j], m), r), gg), bb);
        v = (v >= 0.f) ? v : SLOPEc * v;
        mx = fmaxf(mx, v);
        sm += v;
    }
    for (int off = 16; off; off >>= 1) {
        mx = fmaxf(mx, __shfl_xor_sync(0xffffffffu, mx, off));
        sm += __shfl_xor_sync(0xffffffffu, sm, off);
    }
    if (lane == 0) {
        p[b * 2 * EMBc + o] = mx;
        p[b * 2 * EMBc + EMBc + o] = sm * (1.0f / Nc);
    }
}

__global__ void fc_bn_kernel(const float* __restrict__ in, const float* __restrict__ W,
                             const float* __restrict__ bias, const float* __restrict__ g,
                             const float* __restrict__ bta, float* __restrict__ out,
                             int Cin, int Cout)
{
    int j = blockIdx.x, t = threadIdx.x;
    float a[Bc];
#pragma unroll
    for (int b_ = 0; b_ < Bc; b_++) a[b_] = 0.f;
    for (int e = t; e < Cin; e += 64) {
        float w = W[(size_t)j * Cin + e];
#pragma unroll
        for (int b_ = 0; b_ < Bc; b_++) a[b_] = fmaf(w, in[b_ * Cin + e], a[b_]);
    }
    __shared__ float red[64][Bc];
#pragma unroll
    for (int b_ = 0; b_ < Bc; b_++) red[t][b_] = a[b_];
    __syncthreads();
    for (int s = 32; s > 0; s >>= 1) {
        if (t < s) {
#pragma unroll
            for (int b_ = 0; b_ < Bc; b_++) red[t][b_] += red[t + s][b_];
        }
        __syncthreads();
    }
    if (t < Bc) {
        float bb = bias ? bias[j] : 0.f;
        float vals[Bc];
        double mean = 0.0;
#pragma unroll
        for (int b_ = 0; b_ < Bc; b_++) { vals[b_] = red[0][b_] + bb; mean += (double)vals[b_]; }
        mean *= (1.0 / Bc);
        double var = 0.0;
#pragma unroll
        for (int b_ = 0; b_ < Bc; b_++) { double d = (double)vals[b_] - mean; var += d * d; }
        var *= (1.0 / Bc);
        float m = (float)mean;
        float r = (float)rsqrt(var + EPSc);
        float y = __fadd_rn(__fmul_rn(__fmul_rn(__fsub_rn(vals[t], m), r), g[j]), bta[j]);
        out[t * Cout + j] = (y >= 0.f) ? y : SLOPEc * y;
    }
}

__global__ void fc3_kernel(const float* __restrict__ in, const float* __restrict__ W,
                           const float* __restrict__ bias, float* __restrict__ out)
{
    int t = threadIdx.x;
    if (t >= Bc * 40) return;
    int b = t / 40, j = t % 40;
    float s = 0.f;
    for (int e = 0; e < 256; e++) s = fmaf(W[j * 256 + e], in[b * 256 + e], s);
    out[t] = __fadd_rn(s, bias[j]);
}

// ---------------- host orchestration ----------------

static void run_edge_block(const float* xin, int C, int O,
                           const float* wTseg, const float* g, const float* bta,
                           float* xout,
                           float2* dist, float2* xxp, int* idxp,
                           float* ymax, double* statseg)
{
    xx_kernel<<<(Bc * Nc + 255) / 256, 256>>>(xin, xxp, C);
    dist_sym_kernel<<<dim3(NPAIRS, 1, Bc), 256>>>(xin, xxp, dist, C);
    topk_kernel<<<Bc * Nc, 256>>>(dist, idxp);
    size_t shm = (size_t)(2 * (2 * C * Kc + C)) * sizeof(float) + 2 * Kc * sizeof(int);
    edgeconv_kernel<<<dim3(Nc / 2, Bc), O, shm>>>(xin, wTseg, idxp, ymax, statseg, C, O);
    bnapply_kernel<<<dim3(Nc / 32, O / 32, Bc), dim3(32, 8)>>>(ymax, statseg, g, bta, xout, O,
                                                               1.0 / (double)(Bc * Nc * Kc));
}

extern "C" void kernel_launch(void* const* d_in, const int* in_sizes, int n_in,
                              void* d_out, int out_size)
{
    const float* x   = (const float*)d_in[0];
    const float* w1  = (const float*)d_in[1];
    const float* w2  = (const float*)d_in[2];
    const float* w3  = (const float*)d_in[3];
    const float* w4  = (const float*)d_in[4];
    const float* w5  = (const float*)d_in[5];
    const float* lw1 = (const float*)d_in[6];
    const float* lw2 = (const float*)d_in[7];
    const float* lb2 = (const float*)d_in[8];
    const float* lw3 = (const float*)d_in[9];
    const float* lb3 = (const float*)d_in[10];
    const float* g1 = (const float*)d_in[11]; const float* b1 = (const float*)d_in[12];
    const float* g2 = (const float*)d_in[13]; const float* b2 = (const float*)d_in[14];
    const float* g3 = (const float*)d_in[15]; const float* b3 = (const float*)d_in[16];
    const float* g4 = (const float*)d_in[17]; const float* b4 = (const float*)d_in[18];
    const float* g5 = (const float*)d_in[19]; const float* b5 = (const float*)d_in[20];
    const float* g6 = (const float*)d_in[21]; const float* b6 = (const float*)d_in[22];
    const float* g7 = (const float*)d_in[23]; const float* b7 = (const float*)d_in[24];

    float *wT, *ymax, *x1b, *x2b, *x3b, *x4b, *z5, *pbuf, *h1, *h2;
    float2 *dist, *xxp;
    double* stats;
    int* idxp;
    cudaGetSymbolAddress((void**)&dist,  g_dist2);
    cudaGetSymbolAddress((void**)&xxp,   g_xx2);
    cudaGetSymbolAddress((void**)&idxp,  g_idx);
    cudaGetSymbolAddress((void**)&wT,    g_wT);
    cudaGetSymbolAddress((void**)&ymax,  g_ymax);
    cudaGetSymbolAddress((void**)&stats, g_statsd);
    cudaGetSymbolAddress((void**)&x1b,   g_x1);
    cudaGetSymbolAddress((void**)&x2b,   g_x2);
    cudaGetSymbolAddress((void**)&x3b,   g_x3);
    cudaGetSymbolAddress((void**)&x4b,   g_x4);
    cudaGetSymbolAddress((void**)&z5,    g_z5);
    cudaGetSymbolAddress((void**)&pbuf,  g_p);
    cudaGetSymbolAddress((void**)&h1,    g_h1);
    cudaGetSymbolAddress((void**)&h2,    g_h2);

    transpose_all<<<(90496 + 255) / 256, 256>>>(w1, w2, w3, w4, wT);
    zerostats_kernel<<<12, 256>>>(stats);

    run_edge_block(x,   3,   64,  wT + WT_OFF1, g1, b1, x1b, dist, xxp, idxp, ymax, stats + ST_OFF1);
    run_edge_block(x1b, 64,  64,  wT + WT_OFF2, g2, b2, x2b, dist, xxp, idxp, ymax, stats + ST_OFF2);
    run_edge_block(x2b, 64,  128, wT + WT_OFF3, g3, b3, x3b, dist, xxp, idxp, ymax, stats + ST_OFF3);
    run_edge_block(x3b, 128, 256, wT + WT_OFF4, g4, b4, x4b, dist, xxp, idxp, ymax, stats + ST_OFF4);

    conv5_kernel<<<dim3(Nc / 64, EMBc / 64, Bc), 256>>>(w5, x1b, x2b, x3b, x4b, z5, stats + ST_OFF5);
    pool5_kernel<<<dim3(EMBc, Bc), 32>>>(z5, stats + ST_OFF5, g5, b5, pbuf);

    fc_bn_kernel<<<512, 64>>>(pbuf, lw1, nullptr, g6, b6, h1, 2 * EMBc, 512);
    fc_bn_kernel<<<256, 64>>>(h1, lw2, lb2, g7, b7, h2, 512, 256);
    fc3_kernel<<<1, 320>>>(h2, lw3, lb3, (float*)d_out);
}

// round 16
// speedup vs baseline: 1.6302x; 1.1183x over previous
#include <cuda_runtime.h>
#include <cstdint>
#include <math.h>

#define Bc 8
#define Nc 2048
#define Kc 20
#define EMBc 1024
#define EPSc 1e-5
#define SLOPEc 0.2f

typedef unsigned long long u64;

// ---------------- packed f32x2 helpers (exact dual IEEE fp32 ops) ----------------
__device__ __forceinline__ u64 pack2(float lo, float hi)
{
    u64 r; asm("mov.b64 %0, {%1, %2};" : "=l"(r) : "f"(lo), "f"(hi)); return r;
}
__device__ __forceinline__ void unpack2(u64 v, float& lo, float& hi)
{
    asm("mov.b64 {%0, %1}, %2;" : "=f"(lo), "=f"(hi) : "l"(v));
}
__device__ __forceinline__ u64 fma2(u64 a, u64 b, u64 c)
{
    u64 d; asm("fma.rn.f32x2 %0, %1, %2, %3;" : "=l"(d) : "l"(a), "l"(b), "l"(c)); return d;
}
__device__ __forceinline__ u64 add2(u64 a, u64 b)
{
    u64 d; asm("add.rn.f32x2 %0, %1, %2;" : "=l"(d) : "l"(a), "l"(b)); return d;
}
__device__ __forceinline__ u64 sub2(u64 a, u64 b)
{
    return fma2(b, 0xBF800000BF800000ull, a);
}

// monotone float -> sortable u32 (after -0 -> +0 canonicalization)
__device__ __forceinline__ unsigned sfloat(float f)
{
    unsigned b = __float_as_uint(__fadd_rn(f, 0.0f));   // -0 -> +0 (matches FSETP semantics)
    return b ^ ((unsigned)(((int)b) >> 31) | 0x80000000u);
}

// ---------------- scratch ----------------
__device__ float2 g_dist2[(size_t)Bc * Nc * Nc];
__device__ float2 g_xx2[Bc * Nc];
__device__ int    g_idx[Bc * Nc * Kc];
__device__ float  g_x1[Bc * 64 * Nc];
__device__ float  g_x2[Bc * 64 * Nc];
__device__ float  g_x3[Bc * 128 * Nc];
__device__ float  g_x4[Bc * 256 * Nc];
__device__ float  g_wT[90496];
__device__ float  g_ymax[Bc * Nc * 256];
__device__ double g_statsd[3072];
__device__ float  g_z5[Bc * EMBc * Nc];
__device__ float  g_p[Bc * 2 * EMBc];
__device__ float  g_h1[Bc * 512];
__device__ float  g_h2[Bc * 256];

#define WT_OFF1 0
#define WT_OFF2 384
#define WT_OFF3 8576
#define WT_OFF4 24960
#define ST_OFF1 0
#define ST_OFF2 128
#define ST_OFF3 256
#define ST_OFF4 512
#define ST_OFF5 1024

#define NPAIRS 528   // 32*33/2 lower-triangle 64x64 tile pairs

// ---------------- double-float helpers ----------------
__device__ __forceinline__ void two_sum(float a, float b, float& s, float& e)
{
    s = __fadd_rn(a, b);
    float bp = __fsub_rn(s, a);
    e = __fadd_rn(__fsub_rn(a, __fsub_rn(s, bp)), __fsub_rn(b, bp));
}

__device__ __forceinline__ float2 dd_sub(float ah, float al, float2 b)
{
    float s1  = __fsub_rn(ah, b.x);
    float v   = __fsub_rn(s1, ah);
    float err = __fsub_rn(__fsub_rn(ah, __fsub_rn(s1, v)), __fadd_rn(b.x, v));
    err = __fadd_rn(err, __fsub_rn(al, b.y));
    float hi = __fadd_rn(s1, err);
    float lo = __fsub_rn(err, __fsub_rn(hi, s1));
    return make_float2(hi, lo);
}

// ---------------- kernels ----------------

// w1:(64,6) w2:(64,128) w3:(128,128) w4:(256,256)
__global__ void transpose_all(const float* __restrict__ w1, const float* __restrict__ w2,
                              const float* __restrict__ w3, const float* __restrict__ w4,
                              float* __restrict__ wT)
{
    int t = blockIdx.x * blockDim.x + threadIdx.x;
    const float* w; int O, C2, base, li;
    if (t < 384)        { w = w1; O = 64;  C2 = 6;   base = WT_OFF1; li = t; }
    else if (t < 8576)  { w = w2; O = 64;  C2 = 128; base = WT_OFF2; li = t - 384; }
    else if (t < 24960) { w = w3; O = 128; C2 = 128; base = WT_OFF3; li = t - 8576; }
    else if (t < 90496) { w = w4; O = 256; C2 = 256; base = WT_OFF4; li = t - 24960; }
    else return;
    int o = li / C2, c = li % C2;
    wT[base + c * O + o] = w[li];
}

__global__ void zerostats_kernel(double* __restrict__ stats)
{
    int t = blockIdx.x * blockDim.x + threadIdx.x;
    if (t < 3072) stats[t] = 0.0;
}

__global__ void xx_kernel(const float* __restrict__ x, float2* __restrict__ xx2, int C)
{
    int i = blockIdx.x * blockDim.x + threadIdx.x;
    if (i >= Bc * Nc) return;
    int b = i / Nc, n = i % Nc;
    double s = 0.0;
    for (int c = 0; c < C; c++) {
        double v = (double)x[((size_t)b * C + c) * Nc + n];
        s += v * v;
    }
    float hi = (float)s;
    float lo = (float)(s - (double)hi);
    xx2[i] = make_float2(hi, lo);
}

// symmetric dist: lower-triangle 64x64 tile pairs, each computed once (bit-exact
// dd chains for both orientations). Stores vectorized as float4 pairs.
__global__ void dist_sym_kernel(const float* __restrict__ x, const float2* __restrict__ xx2,
                                float2* __restrict__ dist, int C)
{
    __shared__ float sn[8][64];
    __shared__ float sm_[8][64];
    int b = blockIdx.z;
    int p = blockIdx.x;
    float ff = sqrtf(8.f * (float)p + 1.f);
    int bi = (int)((ff - 1.f) * 0.5f);
    while ((bi + 1) * (bi + 2) / 2 <= p) bi++;
    while (bi * (bi + 1) / 2 > p) bi--;
    int bj = p - bi * (bi + 1) / 2;
    int n0 = bi * 64, m0 = bj * 64;

    int t = threadIdx.x;
    int tx = t & 15, ty = t >> 4;
    u64 s2[4][2], e2[4][2];
#pragma unroll
    for (int i = 0; i < 4; i++)
#pragma unroll
        for (int jp = 0; jp < 2; jp++) { s2[i][jp] = 0ull; e2[i][jp] = 0ull; }
    const float* xb = x + (size_t)b * C * Nc;

    for (int c0 = 0; c0 < C; c0 += 8) {
#pragma unroll
        for (int r = 0; r < 2; r++) {
            int ei = t + r * 256;
            int cc = ei >> 6, j = ei & 63;
            int c = c0 + cc;
            sn[cc][j]  = (c < C) ? xb[(size_t)c * Nc + n0 + j] : 0.f;
            sm_[cc][j] = (c < C) ? xb[(size_t)c * Nc + m0 + j] : 0.f;
        }
        __syncthreads();
        u64 f2[4][2];
#pragma unroll
        for (int i = 0; i < 4; i++) { f2[i][0] = 0ull; f2[i][1] = 0ull; }
#pragma unroll
        for (int q = 0; q < 8; q++) {
            float4 nv = *(const float4*)&sn[q][ty * 4];
            float4 mv = *(const float4*)&sm_[q][tx * 4];
            u64 m01 = pack2(mv.x, mv.y);
            u64 m23 = pack2(mv.z, mv.w);
            float nn[4] = {nv.x, nv.y, nv.z, nv.w};
#pragma unroll
            for (int i = 0; i < 4; i++) {
                u64 np = pack2(nn[i], nn[i]);
                f2[i][0] = fma2(np, m01, f2[i][0]);
                f2[i][1] = fma2(np, m23, f2[i][1]);
            }
        }
#pragma unroll
        for (int i = 0; i < 4; i++)
#pragma unroll
            for (int jp = 0; jp < 2; jp++) {
                u64 tt = add2(s2[i][jp], f2[i][jp]);
                u64 bp = sub2(tt, s2[i][jp]);
                u64 ea = sub2(s2[i][jp], sub2(tt, bp));
                u64 eb = sub2(f2[i][jp], bp);
                e2[i][jp] = add2(e2[i][jp], add2(ea, eb));
                s2[i][jp] = tt;
            }
        __syncthreads();
    }

    float dh[4][4], dl[4][4];
#pragma unroll
    for (int i = 0; i < 4; i++) {
        float sa[4], ea[4];
        unpack2(s2[i][0], sa[0], sa[1]);
        unpack2(s2[i][1], sa[2], sa[3]);
        unpack2(e2[i][0], ea[0], ea[1]);
        unpack2(e2[i][1], ea[2], ea[3]);
#pragma unroll
        for (int j = 0; j < 4; j++) {
            float h, l;
            two_sum(sa[j], ea[j], h, l);
            dh[i][j] = __fmul_rn(h, 2.f);
            dl[i][j] = __fmul_rn(l, 2.f);
        }
    }

    int n = n0 + ty * 4, m = m0 + tx * 4;
    float2 xn[4], xm[4];
#pragma unroll
    for (int i = 0; i < 4; i++) { xn[i] = xx2[b * Nc + n + i]; xm[i] = xx2[b * Nc + m + i]; }
    float2* dr = dist + (size_t)b * Nc * Nc;

#pragma unroll
    for (int i = 0; i < 4; i++) {
        float2 row[4];
#pragma unroll
        for (int j = 0; j < 4; j++) {
            float2 r1 = dd_sub(dh[i][j], dl[i][j], xn[i]);
            row[j] = dd_sub(r1.x, r1.y, xm[j]);
        }
        float4* dst = (float4*)(dr + (size_t)(n + i) * Nc + m);
        dst[0] = make_float4(row[0].x, row[0].y, row[1].x, row[1].y);
        dst[1] = make_float4(row[2].x, row[2].y, row[3].x, row[3].y);
    }

    if (bi != bj) {
#pragma unroll
        for (int j = 0; j < 4; j++) {
            float2 col[4];
#pragma unroll
            for (int i = 0; i < 4; i++) {
                float2 r1 = dd_sub(dh[i][j], dl[i][j], xm[j]);
                col[i] = dd_sub(r1.x, r1.y, xn[i]);
            }
            float4* dst = (float4*)(dr + (size_t)(m + j) * Nc + n);
            dst[0] = make_float4(col[0].x, col[0].y, col[1].x, col[1].y);
            dst[1] = make_float4(col[2].x, col[2].y, col[3].x, col[3].y);
        }
    }
}

// REDUX-based warp argmax pop: returns winner lane (lowest lane among max-key holders)
// and the max key reconstructed from the two 32-bit redux results.
__device__ __forceinline__ int warp_pop(u64 bk, u64& kout)
{
    unsigned hi = (unsigned)(bk >> 32);
    unsigned m1 = __reduce_max_sync(0xffffffffu, hi);
    unsigned lo = (unsigned)bk;
    unsigned cand = (hi == m1) ? lo : 0u;
    unsigned m2 = __reduce_max_sync(0xffffffffu, cand);
    unsigned bal = __ballot_sync(0xffffffffu, (hi == m1) && (lo == m2));
    kout = ((u64)m1 << 32) | m2;
    return __ffs(bal) - 1;
}

// u64-key top-20, 2 rows per 512-thread block. Per-thread Batcher sort of 8 keys,
// REDUX pops (tie -> lowest lane == lowest idx), per-row final merge in its own warp.
#define CEK(i, j) { \
    bool sw = (key[j] > key[i]) || (key[j] == key[i] && vi[j] < vi[i]); \
    if (sw) { u64 tk_ = key[i]; key[i] = key[j]; key[j] = tk_; \
              int ti_ = vi[i]; vi[i] = vi[j]; vi[j] = ti_; } }

__global__ void topk_kernel(const float2* __restrict__ dist, int* __restrict__ idx)
{
    int half = threadIdx.x >> 8;            // which of the 2 rows
    int t = threadIdx.x & 255;
    int row = blockIdx.x * 2 + half;
    int lane = t & 31, wid = t >> 5;        // wid 0..7 within the row
    const float4* d4 = (const float4*)(dist + (size_t)row * Nc) + t * 4;
    u64 key[8];
    int vi[8];
#pragma unroll
    for (int q = 0; q < 4; q++) {
        float4 f = d4[q];
        key[2 * q]     = ((u64)sfloat(f.x) << 32) | sfloat(f.y);
        key[2 * q + 1] = ((u64)sfloat(f.z) << 32) | sfloat(f.w);
        vi[2 * q]     = t * 8 + 2 * q;
        vi[2 * q + 1] = t * 8 + 2 * q + 1;
    }
    // Batcher odd-even mergesort, 8 elements, (key desc, idx asc)
    CEK(0,1) CEK(2,3) CEK(4,5) CEK(6,7)
    CEK(0,2) CEK(1,3) CEK(4,6) CEK(5,7)
    CEK(1,2) CEK(5,6)
    CEK(0,4) CEK(1,5) CEK(2,6) CEK(3,7)
    CEK(2,4) CEK(3,5)
    CEK(1,2) CEK(3,4) CEK(5,6)

    __shared__ u64 swk[2][8][Kc];
    __shared__ int swi[2][8][Kc];

    for (int kk = 0; kk < Kc; kk++) {
        u64 wk;
        int bl = warp_pop(key[0], wk);
        if (lane == 0) swk[half][wid][kk] = wk;
        int widx = __shfl_sync(0xffffffffu, vi[0], bl);
        if (lane == bl) {
            swi[half][wid][kk] = vi[0];
#pragma unroll
            for (int q = 0; q < 7; q++) { key[q] = key[q + 1]; vi[q] = vi[q + 1]; }
            key[7] = 0ull; vi[7] = 0x7FFFFFFF;
        }
        (void)widx;
    }
    __syncthreads();

    if (t < 32) {                           // warp 0 (row A) and warp 8 (row B)
        bool act = lane < 8;
        int pos = 0;
        u64 hk = act ? swk[half][lane][0] : 0ull;
        int hidx = act ? swi[half][lane][0] : 0x7FFFFFFF;
        int* out = idx + (size_t)row * Kc;
        for (int kk = 0; kk < Kc; kk++) {
            u64 wk;
            int bl = warp_pop(hk, wk);
            int widx = __shfl_sync(0xffffffffu, hidx, bl);
            if (lane == 0) out[kk] = widx;
            if (lane == bl) {
                pos++;
                if (act && pos < Kc) { hk = swk[half][lane][pos]; hidx = swi[half][lane][pos]; }
                else                 { hk = 0ull; hidx = 0x7FFFFFFF; }
            }
        }
    }
}

// fused edgeconv: G=2 n per block, LDS.128 feat loads, FFMA2 mainloop (bit-identical
// per-n chains), dd fp32 stat accumulation -> single fp64 atomic per channel pair.
__global__ void edgeconv_kernel(const float* __restrict__ xin, const float* __restrict__ wT,
                                const int* __restrict__ idx, float* __restrict__ ymax,
                                double* __restrict__ stats, int C, int O)
{
    extern __shared__ float shm[];
    int nA = blockIdx.x * 2, nB = nA + 1;
    int b = blockIdx.y, t = threadIdx.x;
    int C2 = 2 * C;
    float* featA = shm;
    float* featB = shm + C2 * Kc;
    float* ctrA  = featB + C2 * Kc;
    float* ctrB  = ctrA + C;
    int*   sidx  = (int*)(ctrB + C);

    if (t < Kc)          sidx[t]     = idx[((size_t)b * Nc + nA) * Kc + t];
    else if (t < 2 * Kc) sidx[t]     = idx[((size_t)b * Nc + nB) * Kc + (t - Kc)];
    for (int c = t; c < C; c += blockDim.x) {
        ctrA[c] = xin[((size_t)b * C + c) * Nc + nA];
        ctrB[c] = xin[((size_t)b * C + c) * Nc + nB];
    }
    __syncthreads();
    for (int e = t; e < C * Kc; e += blockDim.x) {
        int c = e / Kc, k = e - c * Kc;
        float cvA = ctrA[c], cvB = ctrB[c];
        float nvA = xin[((size_t)b * C + c) * Nc + sidx[k]];
        float nvB = xin[((size_t)b * C + c) * Nc + sidx[Kc + k]];
        featA[c * Kc + k]       = __fsub_rn(nvA, cvA);
        featA[(C + c) * Kc + k] = cvA;
        featB[c * Kc + k]       = __fsub_rn(nvB, cvB);
        featB[(C + c) * Kc + k] = cvB;
    }
    __syncthreads();

    u64 accA[Kc / 2], accB[Kc / 2];
#pragma unroll
    for (int p = 0; p < Kc / 2; p++) { accA[p] = 0ull; accB[p] = 0ull; }

    const float* wptr = wT + t;
#pragma unroll 2
    for (int c2 = 0; c2 < C2; c2++) {
        float w = __ldg(wptr + c2 * O);
        u64 wp = pack2(w, w);
        const ulonglong2* fA = reinterpret_cast<const ulonglong2*>(featA + c2 * Kc);
        const ulonglong2* fB = reinterpret_cast<const ulonglong2*>(featB + c2 * Kc);
#pragma unroll
        for (int p = 0; p < 5; p++) {
            ulonglong2 fa = fA[p];
            accA[2 * p]     = fma2(fa.x, wp, accA[2 * p]);
            accA[2 * p + 1] = fma2(fa.y, wp, accA[2 * p + 1]);
        }
#pragma unroll
        for (int p = 0; p < 5; p++) {
            ulonglong2 fb = fB[p];
            accB[2 * p]     = fma2(fb.x, wp, accB[2 * p]);
            accB[2 * p + 1] = fma2(fb.y, wp, accB[2 * p + 1]);
        }
    }

    float acc[Kc];
    double Stot = 0.0, Qtot = 0.0;
#pragma unroll
    for (int half = 0; half < 2; half++) {
        u64* a2 = half ? accB : accA;
#pragma unroll
        for (int p = 0; p < Kc / 2; p++) unpack2(a2[p], acc[2 * p], acc[2 * p + 1]);
        float m = acc[0];
        float s = 0.f, se = 0.f, q = 0.f, qe = 0.f;
#pragma unroll
        for (int k = 0; k < Kc; k++) {
            float a = acc[k];
            m = fmaxf(m, a);
            float th, te;
            two_sum(s, a, th, te);
            s = th; se = __fadd_rn(se, te);
            float ph = __fmul_rn(a, a);
            float pl = fmaf(a, a, -ph);
            two_sum(q, ph, th, te);
            q = th; qe = __fadd_rn(qe, __fadd_rn(te, pl));
        }
        int n = half ? nB : nA;
        ymax[((size_t)b * Nc + n) * O + t] = m;
        Stot += (double)s + (double)se;
        Qtot += (double)q + (double)qe;
    }
    atomicAdd(&stats[t], Stot);
    atomicAdd(&stats[O + t], Qtot);
}

// BN + lrelu on max-pooled values, smem-tile transpose [b][n][o] -> [b][o][n]
__global__ void bnapply_kernel(const float* __restrict__ ymax, const double* __restrict__ stats,
                               const float* __restrict__ g, const float* __restrict__ bta,
                               float* __restrict__ xout, int O, double invcnt)
{
    __shared__ float tile[32][33];
    int b  = blockIdx.z;
    int o0 = blockIdx.y * 32;
    int n0 = blockIdx.x * 32;
    int tx = threadIdx.x, ty = threadIdx.y;
    int o = o0 + tx;
    double mean = stats[o] * invcnt;
    double var  = stats[O + o] * invcnt - mean * mean;
    float m = (float)mean;
    float r = (float)rsqrt(var + EPSc);
    float gg = g[o], bb = bta[o];
#pragma unroll
    for (int rr = 0; rr < 4; rr++) {
        int n = n0 + ty + rr * 8;
        float vv = ymax[((size_t)b * Nc + n) * O + o];
        float y = __fadd_rn(__fmul_rn(__fmul_rn(__fsub_rn(vv, m), r), gg), bb);
        tile[ty + rr * 8][tx] = (y >= 0.f) ? y : SLOPEc * y;
    }
    __syncthreads();
#pragma unroll
    for (int rr = 0; rr < 4; rr++) {
        int oo = o0 + ty + rr * 8;
        xout[((size_t)b * O + oo) * Nc + n0 + tx] = tile[tx][ty + rr * 8];
    }
}

// conv5 with FFMA2 mainloop; dd per-thread stats -> fp64 smem/global atomics
__global__ void conv5_kernel(const float* __restrict__ w5,
                             const float* __restrict__ x1, const float* __restrict__ x2,
                             const float* __restrict__ x3, const float* __restrict__ x4,
                             float* __restrict__ z, double* __restrict__ stats)
{
    __shared__ float As[16][68];
    __shared__ float Bs[16][64];
    __shared__ double rs[64], rss[64];
    int b  = blockIdx.z;
    int o0 = blockIdx.y * 64;
    int n0 = blockIdx.x * 64;
    int t = threadIdx.x;
    int tx = t & 15, ty = t >> 4;
    u64 acc2[4][2];
#pragma unroll
    for (int i = 0; i < 4; i++) { acc2[i][0] = 0ull; acc2[i][1] = 0ull; }

    for (int c0 = 0; c0 < 512; c0 += 16) {
#pragma unroll
        for (int r = 0; r < 4; r++) {
            int e = t + r * 256;
            int oo = e >> 4, cc = e & 15;
            As[cc][oo] = w5[(size_t)(o0 + oo) * 512 + c0 + cc];
            int cc2 = e >> 6, jj = e & 63;
            int ch = c0 + cc2;
            const float* src; int cl, Cb;
            if (ch < 64)       { src = x1; cl = ch;       Cb = 64;  }
            else if (ch < 128) { src = x2; cl = ch - 64;  Cb = 64;  }
            else if (ch < 256) { src = x3; cl = ch - 128; Cb = 128; }
            else               { src = x4; cl = ch - 256; Cb = 256; }
            Bs[cc2][jj] = src[((size_t)b * Cb + cl) * Nc + n0 + jj];
        }
        __syncthreads();
#pragma unroll
        for (int cc = 0; cc < 16; cc++) {
            float4 av4 = *(const float4*)&As[cc][ty * 4];
            float4 bv4 = *(const float4*)&Bs[cc][tx * 4];
            u64 b01 = pack2(bv4.x, bv4.y);
            u64 b23 = pack2(bv4.z, bv4.w);
            float av[4] = {av4.x, av4.y, av4.z, av4.w};
#pragma unroll
            for (int i = 0; i < 4; i++) {
                u64 ap = pack2(av[i], av[i]);
                acc2[i][0] = fma2(ap, b01, acc2[i][0]);
                acc2[i][1] = fma2(ap, b23, acc2[i][1]);
            }
        }
        __syncthreads();
    }
    float acc[4][4];
#pragma unroll
    for (int i = 0; i < 4; i++) {
        unpack2(acc2[i][0], acc[i][0], acc[i][1]);
        unpack2(acc2[i][1], acc[i][2], acc[i][3]);
    }
    if (t < 64) { rs[t] = 0.0; rss[t] = 0.0; }
    __syncthreads();
#pragma unroll
    for (int i = 0; i < 4; i++) {
        int o = o0 + ty * 4 + i;
        float s = 0.f, se = 0.f, q = 0.f, qe = 0.f;
#pragma unroll
        for (int j = 0; j < 4; j++) {
            float a = acc[i][j];
            float th, te;
            two_sum(s, a, th, te);
            s = th; se = __fadd_rn(se, te);
            float ph = __fmul_rn(a, a);
            float pl = fmaf(a, a, -ph);
            two_sum(q, ph, th, te);
            q = th; qe = __fadd_rn(qe, __fadd_rn(te, pl));
        }
        atomicAdd(&rs[ty * 4 + i],  (double)s + (double)se);
        atomicAdd(&rss[ty * 4 + i], (double)q + (double)qe);
        float4 v4 = make_float4(acc[i][0], acc[i][1], acc[i][2], acc[i][3]);
        *reinterpret_cast<float4*>(&z[((size_t)b * EMBc + o) * Nc + n0 + tx * 4]) = v4;
    }
    __syncthreads();
    if (t < 64) {
        atomicAdd(&stats[o0 + t], rs[t]);
        atomicAdd(&stats[EMBc + o0 + t], rss[t]);
    }
}

__global__ void pool5_kernel(const float* __restrict__ z, const double* __restrict__ stats,
                             const float* __restrict__ g, const float* __restrict__ bta,
                             float* __restrict__ p)
{
    int o = blockIdx.x, b = blockIdx.y, lane = threadIdx.x;
    const double inv = 1.0 / (double)(Bc * Nc);
    double mean = stats[o] * inv;
    double var  = stats[EMBc + o] * inv - mean * mean;
    float m = (float)mean;
    float r = (float)rsqrt(var + EPSc);
    float gg = g[o], bb = bta[o];
    const float* row = z + ((size_t)b * EMBc + o) * Nc;
    float mx = -INFINITY, sm = 0.f;
    for (int j = lane; j < Nc; j += 32) {
        float v = __fadd_rn(__fmul_rn(__fmul_rn(__fsub_rn(row[j], m), r), gg), bb);
        v = (v >= 0.f) ? v : SLOPEc * v;
        mx = fmaxf(mx, v);
        sm += v;
    }
    for (int off = 16; off; off >>= 1) {
        mx = fmaxf(mx, __shfl_xor_sync(0xffffffffu, mx, off));
        sm += __shfl_xor_sync(0xffffffffu, sm, off);
    }
    if (lane == 0) {
        p[b * 2 * EMBc + o] = mx;
        p[b * 2 * EMBc + EMBc + o] = sm * (1.0f / Nc);
    }
}

__global__ void fc_bn_kernel(const float* __restrict__ in, const float* __restrict__ W,
                             const float* __restrict__ bias, const float* __restrict__ g,
                             const float* __restrict__ bta, float* __restrict__ out,
                             int Cin, int Cout)
{
    int j = blockIdx.x, t = threadIdx.x;
    float a[Bc];
#pragma unroll
    for (int b_ = 0; b_ < Bc; b_++) a[b_] = 0.f;
    for (int e = t; e < Cin; e += 64) {
        float w = W[(size_t)j * Cin + e];
#pragma unroll
        for (int b_ = 0; b_ < Bc; b_++) a[b_] = fmaf(w, in[b_ * Cin + e], a[b_]);
    }
    __shared__ float red[64][Bc];
#pragma unroll
    for (int b_ = 0; b_ < Bc; b_++) red[t][b_] = a[b_];
    __syncthreads();
    for (int s = 32; s > 0; s >>= 1) {
        if (t < s) {
#pragma unroll
            for (int b_ = 0; b_ < Bc; b_++) red[t][b_] += red[t + s][b_];
        }
        __syncthreads();
    }
    if (t < Bc) {
        float bb = bias ? bias[j] : 0.f;
        float vals[Bc];
        double mean = 0.0;
#pragma unroll
        for (int b_ = 0; b_ < Bc; b_++) { vals[b_] = red[0][b_] + bb; mean += (double)vals[b_]; }
        mean *= (1.0 / Bc);
        double var = 0.0;
#pragma unroll
        for (int b_ = 0; b_ < Bc; b_++) { double d = (double)vals[b_] - mean; var += d * d; }
        var *= (1.0 / Bc);
        float m = (float)mean;
        float r = (float)rsqrt(var + EPSc);
        float y = __fadd_rn(__fmul_rn(__fmul_rn(__fsub_rn(vals[t], m), r), g[j]), bta[j]);
        out[t * Cout + j] = (y >= 0.f) ? y : SLOPEc * y;
    }
}

__global__ void fc3_kernel(const float* __restrict__ in, const float* __restrict__ W,
                           const float* __restrict__ bias, float* __restrict__ out)
{
    int t = threadIdx.x;
    if (t >= Bc * 40) return;
    int b = t / 40, j = t % 40;
    float s = 0.f;
    for (int e = 0; e < 256; e++) s = fmaf(W[j * 256 + e], in[b * 256 + e], s);
    out[t] = __fadd_rn(s, bias[j]);
}

// ---------------- host orchestration ----------------

static void run_edge_block(const float* xin, int C, int O,
                           const float* wTseg, const float* g, const float* bta,
                           float* xout,
                           float2* dist, float2* xxp, int* idxp,
                           float* ymax, double* statseg)
{
    xx_kernel<<<(Bc * Nc + 255) / 256, 256>>>(xin, xxp, C);
    dist_sym_kernel<<<dim3(NPAIRS, 1, Bc), 256>>>(xin, xxp, dist, C);
    topk_kernel<<<Bc * Nc / 2, 512>>>(dist, idxp);
    size_t shm = (size_t)(2 * (2 * C * Kc + C)) * sizeof(float) + 2 * Kc * sizeof(int);
    edgeconv_kernel<<<dim3(Nc / 2, Bc), O, shm>>>(xin, wTseg, idxp, ymax, statseg, C, O);
    bnapply_kernel<<<dim3(Nc / 32, O / 32, Bc), dim3(32, 8)>>>(ymax, statseg, g, bta, xout, O,
                                                               1.0 / (double)(Bc * Nc * Kc));
}

extern "C" void kernel_launch(void* const* d_in, const int* in_sizes, int n_in,
                              void* d_out, int out_size)
{
    const float* x   = (const float*)d_in[0];
    const float* w1  = (const float*)d_in[1];
    const float* w2  = (const float*)d_in[2];
    const float* w3  = (const float*)d_in[3];
    const float* w4  = (const float*)d_in[4];
    const float* w5  = (const float*)d_in[5];
    const float* lw1 = (const float*)d_in[6];
    const float* lw2 = (const float*)d_in[7];
    const float* lb2 = (const float*)d_in[8];
    const float* lw3 = (const float*)d_in[9];
    const float* lb3 = (const float*)d_in[10];
    const float* g1 = (const float*)d_in[11]; const float* b1 = (const float*)d_in[12];
    const float* g2 = (const float*)d_in[13]; const float* b2 = (const float*)d_in[14];
    const float* g3 = (const float*)d_in[15]; const float* b3 = (const float*)d_in[16];
    const float* g4 = (const float*)d_in[17]; const float* b4 = (const float*)d_in[18];
    const float* g5 = (const float*)d_in[19]; const float* b5 = (const float*)d_in[20];
    const float* g6 = (const float*)d_in[21]; const float* b6 = (const float*)d_in[22];
    const float* g7 = (const float*)d_in[23]; const float* b7 = (const float*)d_in[24];

    float *wT, *ymax, *x1b, *x2b, *x3b, *x4b, *z5, *pbuf, *h1, *h2;
    float2 *dist, *xxp;
    double* stats;
    int* idxp;
    cudaGetSymbolAddress((void**)&dist,  g_dist2);
    cudaGetSymbolAddress((void**)&xxp,   g_xx2);
    cudaGetSymbolAddress((void**)&idxp,  g_idx);
    cudaGetSymbolAddress((void**)&wT,    g_wT);
    cudaGetSymbolAddress((void**)&ymax,  g_ymax);
    cudaGetSymbolAddress((void**)&stats, g_statsd);
    cudaGetSymbolAddress((void**)&x1b,   g_x1);
    cudaGetSymbolAddress((void**)&x2b,   g_x2);
    cudaGetSymbolAddress((void**)&x3b,   g_x3);
    cudaGetSymbolAddress((void**)&x4b,   g_x4);
    cudaGetSymbolAddress((void**)&z5,    g_z5);
    cudaGetSymbolAddress((void**)&pbuf,  g_p);
    cudaGetSymbolAddress((void**)&h1,    g_h1);
    cudaGetSymbolAddress((void**)&h2,    g_h2);

    transpose_all<<<(90496 + 255) / 256, 256>>>(w1, w2, w3, w4, wT);
    zerostats_kernel<<<12, 256>>>(stats);

    run_edge_block(x,   3,   64,  wT + WT_OFF1, g1, b1, x1b, dist, xxp, idxp, ymax, stats + ST_OFF1);
    run_edge_block(x1b, 64,  64,  wT + WT_OFF2, g2, b2, x2b, dist, xxp, idxp, ymax, stats + ST_OFF2);
    run_edge_block(x2b, 64,  128, wT + WT_OFF3, g3, b3, x3b, dist, xxp, idxp, ymax, stats + ST_OFF3);
    run_edge_block(x3b, 128, 256, wT + WT_OFF4, g4, b4, x4b, dist, xxp, idxp, ymax, stats + ST_OFF4);

    conv5_kernel<<<dim3(Nc / 64, EMBc / 64, Bc), 256>>>(w5, x1b, x2b, x3b, x4b, z5, stats + ST_OFF5);
    pool5_kernel<<<dim3(EMBc, Bc), 32>>>(z5, stats + ST_OFF5, g5, b5, pbuf);

    fc_bn_kernel<<<512, 64>>>(pbuf, lw1, nullptr, g6, b6, h1, 2 * EMBc, 512);
    fc_bn_kernel<<<256, 64>>>(h1, lw2, lb2, g7, b7, h2, 512, 256);
    fc3_kernel<<<1, 320>>>(h2, lw3, lb3, (float*)d_out);
}